// round 11
// baseline (speedup 1.0000x reference)
#include <cuda_runtime.h>
#include <cuda_bf16.h>
#include <math.h>
#include <cstdint>

// ---------------------------------------------------------------------------
// Encoder_84413287236054 : fp32 transformer encoder layer on GB300
// Round 11: cp.async (LDGSTS) pipelines in GEMM + attention mainloops.
// Math identical to R10 (bf16 hi/lo 3-MMA, fp32 softmax).
// ---------------------------------------------------------------------------

#define TOK  4096
#define DIM  1024
#define DFF  4096
#define NH   16
#define HD   64
#define SEQ  2048
#define BATCH 2

typedef unsigned long long u64;
typedef __nv_bfloat16 bf16;

// ---- tensor-core primitives (compute_103-legal) ----------------------------
__device__ __forceinline__ uint32_t smem_u32(const void* p) {
    uint32_t a;
    asm("{ .reg .u64 t; cvta.to.shared.u64 t, %1; cvt.u32.u64 %0, t; }" : "=r"(a) : "l"(p));
    return a;
}
__device__ __forceinline__ void ldmx4(uint32_t* r, uint32_t addr) {
    asm volatile("ldmatrix.sync.aligned.m8n8.x4.shared.b16 {%0,%1,%2,%3},[%4];"
        : "=r"(r[0]), "=r"(r[1]), "=r"(r[2]), "=r"(r[3]) : "r"(addr));
}
__device__ __forceinline__ void ldmx4t(uint32_t* r, uint32_t addr) {
    asm volatile("ldmatrix.sync.aligned.m8n8.x4.trans.shared.b16 {%0,%1,%2,%3},[%4];"
        : "=r"(r[0]), "=r"(r[1]), "=r"(r[2]), "=r"(r[3]) : "r"(addr));
}
__device__ __forceinline__ void mma_bf16(float* c, const uint32_t* a, const uint32_t* b) {
    asm volatile("mma.sync.aligned.m16n8k16.row.col.f32.bf16.bf16.f32 "
        "{%0,%1,%2,%3},{%4,%5,%6,%7},{%8,%9},{%0,%1,%2,%3};"
        : "+f"(c[0]), "+f"(c[1]), "+f"(c[2]), "+f"(c[3])
        : "r"(a[0]), "r"(a[1]), "r"(a[2]), "r"(a[3]), "r"(b[0]), "r"(b[1]));
}
__device__ __forceinline__ void cp16(uint32_t dst, const void* src) {
    asm volatile("cp.async.cg.shared.global [%0],[%1],16;" :: "r"(dst), "l"(src));
}
#define CP_COMMIT() asm volatile("cp.async.commit_group;" ::: "memory")
#define CP_WAIT0()  asm volatile("cp.async.wait_group 0;" ::: "memory")

__device__ __forceinline__ void split1(float x, bf16& h, bf16& l) {
    h = __float2bfloat16(x);
    l = __float2bfloat16(x - __bfloat162float(h));
}
__device__ __forceinline__ uint32_t packbf2(bf16 a, bf16 b) {
    __nv_bfloat162 t = __halves2bfloat162(a, b);
    return *(uint32_t*)&t;
}
__device__ __forceinline__ void split2pack(float a, float b, uint32_t& hp, uint32_t& lp) {
    bf16 ha, la, hb, lb;
    split1(a, ha, la); split1(b, hb, lb);
    hp = packbf2(ha, hb); lp = packbf2(la, lb);
}

// ---------------- scratch (allocation-free) ---------------------------------
__device__ bf16  g_hh [TOK * DIM], g_hl [TOK * DIM];
__device__ bf16  g_qh [TOK * DIM], g_ql [TOK * DIM];
__device__ bf16  g_kh [TOK * DIM], g_kl [TOK * DIM];
__device__ bf16  g_vh [TOK * DIM], g_vl [TOK * DIM];
__device__ bf16  g_ath[TOK * DIM], g_atl[TOK * DIM];
__device__ float g_x1 [TOK * DIM];
__device__ bf16  g_h2h[TOK * DIM], g_h2l[TOK * DIM];
__device__ bf16  g_ffh[TOK * DFF], g_ffl[TOK * DFF];
__device__ bf16 g_wqh[DIM * DIM], g_wql[DIM * DIM];
__device__ bf16 g_wkh[DIM * DIM], g_wkl[DIM * DIM];
__device__ bf16 g_wvh[DIM * DIM], g_wvl[DIM * DIM];
__device__ bf16 g_woh[DIM * DIM], g_wol[DIM * DIM];
__device__ bf16 g_w1h[DFF * DIM], g_w1l[DFF * DIM];
__device__ bf16 g_w2h[DIM * DFF], g_w2l[DIM * DFF];

// ---------------------------------------------------------------------------
// Weight transpose + hi/lo split: W[K,N] fp32 -> Th,Tl [N,K] bf16
// ---------------------------------------------------------------------------
__global__ __launch_bounds__(256) void wsplit(
    const float* __restrict__ W, bf16* __restrict__ Th, bf16* __restrict__ Tl,
    int K, int N)
{
    __shared__ float t[32][33];
    const int n0 = blockIdx.x * 32, k0 = blockIdx.y * 32;
    const int tx = threadIdx.x & 31, ty = threadIdx.x >> 5;
    #pragma unroll
    for (int i = ty; i < 32; i += 8)
        t[i][tx] = W[(size_t)(k0 + i) * N + n0 + tx];
    __syncthreads();
    #pragma unroll
    for (int i = ty; i < 32; i += 8) {
        const float x = t[tx][i];
        bf16 h, l; split1(x, h, l);
        Th[(size_t)(n0 + i) * K + k0 + tx] = h;
        Tl[(size_t)(n0 + i) * K + k0 + tx] = l;
    }
}

// ---------------------------------------------------------------------------
// LayerNorm -> bf16 hi/lo
// ---------------------------------------------------------------------------
__global__ __launch_bounds__(256) void ln_split(
    const float* __restrict__ x, const float* __restrict__ g,
    const float* __restrict__ b, bf16* __restrict__ oh, bf16* __restrict__ ol)
{
    const int row = blockIdx.x;
    const int t = threadIdx.x;
    const float4 v = ((const float4*)(x + (size_t)row * DIM))[t];

    float s  = v.x + v.y + v.z + v.w;
    float ss = v.x*v.x + v.y*v.y + v.z*v.z + v.w*v.w;
    #pragma unroll
    for (int o = 16; o; o >>= 1) {
        s  += __shfl_xor_sync(0xffffffffu, s,  o);
        ss += __shfl_xor_sync(0xffffffffu, ss, o);
    }
    __shared__ float sm[8], sm2[8];
    if ((t & 31) == 0) { sm[t >> 5] = s; sm2[t >> 5] = ss; }
    __syncthreads();
    float ts = 0.f, tss = 0.f;
    #pragma unroll
    for (int i = 0; i < 8; i++) { ts += sm[i]; tss += sm2[i]; }

    const float mu   = ts * (1.0f / DIM);
    const float rstd = rsqrtf(tss * (1.0f / DIM) - mu * mu + 1e-5f);
    const float4 gv = ((const float4*)g)[t];
    const float4 bv = ((const float4*)b)[t];
    float y[4];
    y[0] = (v.x - mu) * rstd * gv.x + bv.x;
    y[1] = (v.y - mu) * rstd * gv.y + bv.y;
    y[2] = (v.z - mu) * rstd * gv.z + bv.z;
    y[3] = (v.w - mu) * rstd * gv.w + bv.w;
    uint32_t hp0, lp0, hp1, lp1;
    split2pack(y[0], y[1], hp0, lp0);
    split2pack(y[2], y[3], hp1, lp1);
    *(uint2*)(oh + (size_t)row * DIM + t * 4) = make_uint2(hp0, hp1);
    *(uint2*)(ol + (size_t)row * DIM + t * 4) = make_uint2(lp0, lp1);
}

// ---------------------------------------------------------------------------
// Tensor-core GEMM with cp.async double-buffered pipeline.
// C[M,N] = (Ah+Al)[M,K] @ (Bh+Bl)^T   (B stored [N,K])
// ---------------------------------------------------------------------------
#define ARR_B  10240u
#define BUFSZ  40960u
#define MM_SMEM (2u * BUFSZ)

template<int EPI>
__global__ __launch_bounds__(256, 1) void mm_tc(
    const bf16* __restrict__ Ah, const bf16* __restrict__ Al,
    const bf16* __restrict__ Bh, const bf16* __restrict__ Bl,
    const float* __restrict__ bias, const float* __restrict__ res,
    float* __restrict__ C, bf16* __restrict__ Ch, bf16* __restrict__ Cl,
    int M, int N, int K, float oscale)
{
    extern __shared__ char smem[];
    const uint32_t sb = smem_u32(smem);
    const int tid = threadIdx.x, wid = tid >> 5, lid = tid & 31;
    const int wm = wid & 1, wn = wid >> 1;
    const int m0 = blockIdx.y * 128, n0 = blockIdx.x * 128;

    const int r0_ = tid >> 2, c0_ = tid & 3;
    const int r1_ = r0_ + 64;

    const bf16* srcs[4] = { Ah, Al, Bh, Bl };
    const int   base4[4] = { m0, m0, n0, n0 };

    // cp.async an entire K32 chunk into buffer (8 x 16B per thread)
    auto cpChunk = [&](int kt, int buf) {
        const uint32_t bb = sb + buf * BUFSZ;
        #pragma unroll
        for (int a = 0; a < 4; a++) {
            const bf16* s = srcs[a] + (size_t)base4[a] * K + kt * 32;
            cp16(bb + a * ARR_B + r0_ * 80 + c0_ * 16, s + (size_t)r0_ * K + c0_ * 8);
            cp16(bb + a * ARR_B + r1_ * 80 + c0_ * 16, s + (size_t)r1_ * K + c0_ * 8);
        }
        CP_COMMIT();
    };

    float acc[4][4][4] = {};

    const int arow = wm * 64 + (lid & 7) + ((lid >> 3) & 1) * 8;
    const uint32_t acolb = ((lid >> 4) & 1) * 16;
    const int brow = wn * 32 + (lid & 7) + ((lid >> 4) & 1) * 8;
    const uint32_t bcolb = ((lid >> 3) & 1) * 16;

    cpChunk(0, 0);
    CP_WAIT0();
    __syncthreads();

    const int nk = K >> 5;
    for (int kt = 0; kt < nk; kt++) {
        const int buf = kt & 1;
        if (kt + 1 < nk) cpChunk(kt + 1, buf ^ 1);

        const uint32_t bb = sb + buf * BUFSZ;
        #pragma unroll
        for (int kh = 0; kh < 2; kh++) {
            uint32_t ah[4][4], al[4][4], bh[4][2], bl[4][2];
            #pragma unroll
            for (int mf = 0; mf < 4; mf++) {
                const uint32_t ad = bb + (arow + mf * 16) * 80 + acolb + kh * 32;
                ldmx4(ah[mf], ad);
                ldmx4(al[mf], ad + ARR_B);
            }
            #pragma unroll
            for (int g2 = 0; g2 < 2; g2++) {
                const uint32_t bd = bb + 2 * ARR_B + (brow + g2 * 16) * 80 + bcolb + kh * 32;
                uint32_t t[4];
                ldmx4(t, bd);
                bh[g2*2][0] = t[0]; bh[g2*2][1] = t[1];
                bh[g2*2+1][0] = t[2]; bh[g2*2+1][1] = t[3];
                ldmx4(t, bd + ARR_B);
                bl[g2*2][0] = t[0]; bl[g2*2][1] = t[1];
                bl[g2*2+1][0] = t[2]; bl[g2*2+1][1] = t[3];
            }
            #pragma unroll
            for (int mf = 0; mf < 4; mf++)
                #pragma unroll
                for (int nf = 0; nf < 4; nf++) {
                    mma_bf16(acc[mf][nf], ah[mf], bh[nf]);
                    mma_bf16(acc[mf][nf], ah[mf], bl[nf]);
                    mma_bf16(acc[mf][nf], al[mf], bh[nf]);
                }
        }

        if (kt + 1 < nk) {
            CP_WAIT0();
            __syncthreads();
        }
    }

    // ---------------- epilogue ----------------
    #pragma unroll
    for (int mf = 0; mf < 4; mf++) {
        const int rowA = m0 + wm * 64 + mf * 16 + (lid >> 2);
        const int rowB = rowA + 8;
        #pragma unroll
        for (int nf = 0; nf < 4; nf++) {
            const int col = n0 + wn * 32 + nf * 8 + (lid & 3) * 2;
            const float2 b2 = *(const float2*)(bias + col);
            float v0 = acc[mf][nf][0] + b2.x;
            float v1 = acc[mf][nf][1] + b2.y;
            float v2 = acc[mf][nf][2] + b2.x;
            float v3 = acc[mf][nf][3] + b2.y;
            const size_t offA = (size_t)rowA * N + col;
            const size_t offB = (size_t)rowB * N + col;
            if (EPI == 1) {
                const float2 rA = *(const float2*)(res + offA);
                const float2 rB = *(const float2*)(res + offB);
                v0 += rA.x; v1 += rA.y; v2 += rB.x; v3 += rB.y;
            }
            if (EPI == 2 || EPI == 3) {
                if (EPI == 2) {
                    v0 = v0 * normcdff(v0); v1 = v1 * normcdff(v1);
                    v2 = v2 * normcdff(v2); v3 = v3 * normcdff(v3);
                } else {
                    v0 *= oscale; v1 *= oscale; v2 *= oscale; v3 *= oscale;
                }
                uint32_t hA, lA, hB, lB;
                split2pack(v0, v1, hA, lA);
                split2pack(v2, v3, hB, lB);
                *(uint32_t*)(Ch + offA) = hA;
                *(uint32_t*)(Cl + offA) = lA;
                *(uint32_t*)(Ch + offB) = hB;
                *(uint32_t*)(Cl + offB) = lB;
            } else {
                *(float2*)(C + offA) = make_float2(v0, v1);
                *(float2*)(C + offB) = make_float2(v2, v3);
            }
        }
    }
}

// ---------------------------------------------------------------------------
// Flash attention v3: cp.async double-buffered K/V. Math identical to R10.
// Grid (SEQ/128, B*NH). Block 256 = 8 warps; warp = 16 q-rows.
// ---------------------------------------------------------------------------
#define AQ_B   18432u                   // 128 * 144
#define AKV_B  9216u                    // 64 * 144
#define KV0    (2u * AQ_B)
#define KVBUF  (4u * AKV_B)
#define ASMEM  (KV0 + 2u * KVBUF)       // 110592

__global__ __launch_bounds__(256, 1) void attn_tc(
    const bf16* __restrict__ qh, const bf16* __restrict__ ql,
    const bf16* __restrict__ kh, const bf16* __restrict__ kl,
    const bf16* __restrict__ vh, const bf16* __restrict__ vl,
    bf16* __restrict__ oh, bf16* __restrict__ ol)
{
    extern __shared__ char smem[];
    const uint32_t sb = smem_u32(smem);
    const int tid = threadIdx.x, wid = tid >> 5, lid = tid & 31;
    const int bh_ = blockIdx.y;
    const int b = bh_ >> 4, h = bh_ & 15;
    const int q0 = blockIdx.x * 128;
    const size_t base = (size_t)(b * SEQ) * DIM + h * HD;

    // cp.async a 64-row K/V tile into buffer (8 x 16B per thread)
    auto cpKV = [&](int kt, int buf) {
        const size_t rowb = base + (size_t)(kt * 64) * DIM;
        const uint32_t bb = sb + KV0 + buf * KVBUF;
        #pragma unroll
        for (int u = 0; u < 2; u++) {
            const int idx = u * 256 + tid;
            const int r = idx >> 3, c8 = idx & 7;
            const size_t gp = rowb + (size_t)r * DIM + c8 * 8;
            const uint32_t so = r * 144 + c8 * 16;
            cp16(bb + 0*AKV_B + so, kh + gp);
            cp16(bb + 1*AKV_B + so, kl + gp);
            cp16(bb + 2*AKV_B + so, vh + gp);
            cp16(bb + 3*AKV_B + so, vl + gp);
        }
        CP_COMMIT();
    };

    // ---- stage Q tile (128 rows) + first K/V tile ----
    cpKV(0, 0);
    #pragma unroll
    for (int it = 0; it < 4; it++) {
        const int idx = it * 256 + tid;
        const int r = idx >> 3, c8 = idx & 7;
        const size_t gp = base + (size_t)(q0 + r) * DIM + c8 * 8;
        *(uint4*)(smem + 0      + r * 144 + c8 * 16) = *(const uint4*)(qh + gp);
        *(uint4*)(smem + AQ_B   + r * 144 + c8 * 16) = *(const uint4*)(ql + gp);
    }
    CP_WAIT0();
    __syncthreads();

    // ---- per-warp Q A-fragments ----
    uint32_t Qh_[4][4], Ql_[4][4];
    const int arow = wid * 16 + (lid & 7) + ((lid >> 3) & 1) * 8;
    const uint32_t acol = ((lid >> 4) & 1) * 16;
    #pragma unroll
    for (int ks = 0; ks < 4; ks++) {
        const uint32_t ad = sb + arow * 144 + acol + ks * 32;
        ldmx4(Qh_[ks], ad);
        ldmx4(Ql_[ks], ad + AQ_B);
    }

    float O[8][4] = {};
    float m0_ = -1e30f, m1_ = -1e30f, l0_ = 0.f, l1_ = 0.f;

    const int brow = (lid & 7) + ((lid >> 4) & 1) * 8;
    const uint32_t bcol = ((lid >> 3) & 1) * 16;
    const int vrow = (lid & 7) + ((lid >> 3) & 1) * 8;
    const uint32_t vcole = ((lid >> 4) & 1) * 8;

    const int NT = SEQ / 64;
    for (int kt = 0; kt < NT; kt++) {
        const int buf = kt & 1;
        if (kt + 1 < NT) cpKV(kt + 1, buf ^ 1);

        const uint32_t kvb = sb + KV0 + buf * KVBUF;

        // ---- scores S = Q K^T (3-MMA hi/lo) ----
        float S[8][4] = {};
        #pragma unroll
        for (int ks = 0; ks < 4; ks++) {
            #pragma unroll
            for (int g2 = 0; g2 < 4; g2++) {
                const uint32_t bd = kvb + (brow + g2 * 16) * 144 + bcol + ks * 32;
                uint32_t th[4], tl[4];
                ldmx4(th, bd);
                ldmx4(tl, bd + AKV_B);
                uint32_t bh0[2] = { th[0], th[1] }, bh1[2] = { th[2], th[3] };
                uint32_t bl0[2] = { tl[0], tl[1] }, bl1[2] = { tl[2], tl[3] };
                mma_bf16(S[g2*2],   Qh_[ks], bh0);
                mma_bf16(S[g2*2],   Qh_[ks], bl0);
                mma_bf16(S[g2*2],   Ql_[ks], bh0);
                mma_bf16(S[g2*2+1], Qh_[ks], bh1);
                mma_bf16(S[g2*2+1], Qh_[ks], bl1);
                mma_bf16(S[g2*2+1], Ql_[ks], bh1);
            }
        }

        // ---- online softmax ----
        float rm0 = -1e30f, rm1 = -1e30f;
        #pragma unroll
        for (int nf = 0; nf < 8; nf++) {
            rm0 = fmaxf(rm0, fmaxf(S[nf][0], S[nf][1]));
            rm1 = fmaxf(rm1, fmaxf(S[nf][2], S[nf][3]));
        }
        rm0 = fmaxf(rm0, __shfl_xor_sync(0xffffffffu, rm0, 1));
        rm0 = fmaxf(rm0, __shfl_xor_sync(0xffffffffu, rm0, 2));
        rm1 = fmaxf(rm1, __shfl_xor_sync(0xffffffffu, rm1, 1));
        rm1 = fmaxf(rm1, __shfl_xor_sync(0xffffffffu, rm1, 2));
        const float mn0 = fmaxf(m0_, rm0), mn1 = fmaxf(m1_, rm1);
        const float c0 = __expf(m0_ - mn0), c1 = __expf(m1_ - mn1);
        m0_ = mn0; m1_ = mn1;

        float rs0 = 0.f, rs1 = 0.f;
        #pragma unroll
        for (int nf = 0; nf < 8; nf++) {
            S[nf][0] = __expf(S[nf][0] - mn0);
            S[nf][1] = __expf(S[nf][1] - mn0);
            S[nf][2] = __expf(S[nf][2] - mn1);
            S[nf][3] = __expf(S[nf][3] - mn1);
            rs0 += S[nf][0] + S[nf][1];
            rs1 += S[nf][2] + S[nf][3];
        }
        rs0 += __shfl_xor_sync(0xffffffffu, rs0, 1);
        rs0 += __shfl_xor_sync(0xffffffffu, rs0, 2);
        rs1 += __shfl_xor_sync(0xffffffffu, rs1, 1);
        rs1 += __shfl_xor_sync(0xffffffffu, rs1, 2);
        l0_ = l0_ * c0 + rs0;
        l1_ = l1_ * c1 + rs1;
        #pragma unroll
        for (int nf = 0; nf < 8; nf++) {
            O[nf][0] *= c0; O[nf][1] *= c0;
            O[nf][2] *= c1; O[nf][3] *= c1;
        }

        // ---- P fragments (hi/lo) from S ----
        uint32_t Ph[4][4], Pl[4][4];
        #pragma unroll
        for (int t = 0; t < 4; t++) {
            split2pack(S[2*t][0],   S[2*t][1],   Ph[t][0], Pl[t][0]);
            split2pack(S[2*t][2],   S[2*t][3],   Ph[t][1], Pl[t][1]);
            split2pack(S[2*t+1][0], S[2*t+1][1], Ph[t][2], Pl[t][2]);
            split2pack(S[2*t+1][2], S[2*t+1][3], Ph[t][3], Pl[t][3]);
        }

        // ---- O += P V (3-MMA hi/lo), V row-major via ldmatrix.trans ----
        #pragma unroll
        for (int t = 0; t < 4; t++) {
            #pragma unroll
            for (int g2 = 0; g2 < 4; g2++) {
                const uint32_t vd = kvb + 2*AKV_B +
                    (t * 16 + vrow) * 144 + (g2 * 16 + vcole) * 2;
                uint32_t th[4], tl[4];
                ldmx4t(th, vd);
                ldmx4t(tl, vd + AKV_B);
                uint32_t bh0[2] = { th[0], th[1] }, bh1[2] = { th[2], th[3] };
                uint32_t bl0[2] = { tl[0], tl[1] }, bl1[2] = { tl[2], tl[3] };
                mma_bf16(O[g2*2],   Ph[t], bh0);
                mma_bf16(O[g2*2],   Pl[t], bh0);
                mma_bf16(O[g2*2],   Ph[t], bl0);
                mma_bf16(O[g2*2+1], Ph[t], bh1);
                mma_bf16(O[g2*2+1], Pl[t], bh1);
                mma_bf16(O[g2*2+1], Ph[t], bl1);
            }
        }

        if (kt + 1 < NT) {
            CP_WAIT0();
            __syncthreads();
        }
    }

    // ---- epilogue: normalize + bf16 hi/lo store ----
    const float inv0 = 1.f / l0_, inv1 = 1.f / l1_;
    const int rowA = q0 + wid * 16 + (lid >> 2);
    const int rowB = rowA + 8;
    #pragma unroll
    for (int nf = 0; nf < 8; nf++) {
        const int col = h * HD + nf * 8 + (lid & 3) * 2;
        const size_t offA = (size_t)(b * SEQ + rowA) * DIM + col;
        const size_t offB = (size_t)(b * SEQ + rowB) * DIM + col;
        uint32_t hA, lA, hB, lB;
        split2pack(O[nf][0] * inv0, O[nf][1] * inv0, hA, lA);
        split2pack(O[nf][2] * inv1, O[nf][3] * inv1, hB, lB);
        *(uint32_t*)(oh + offA) = hA;
        *(uint32_t*)(ol + offA) = lA;
        *(uint32_t*)(oh + offB) = hB;
        *(uint32_t*)(ol + offB) = lB;
    }
}

// ---------------------------------------------------------------------------
extern "C" void kernel_launch(void* const* d_in, const int* in_sizes, int n_in,
                              void* d_out, int out_size)
{
    const float* x     = (const float*)d_in[0];
    const float* ln1_g = (const float*)d_in[1];
    const float* ln1_b = (const float*)d_in[2];
    const float* wq = (const float*)d_in[3];
    const float* bq = (const float*)d_in[4];
    const float* wk = (const float*)d_in[5];
    const float* bk = (const float*)d_in[6];
    const float* wv = (const float*)d_in[7];
    const float* bv = (const float*)d_in[8];
    const float* wo = (const float*)d_in[9];
    const float* bo = (const float*)d_in[10];
    const float* w1 = (const float*)d_in[11];
    const float* b1 = (const float*)d_in[12];
    const float* w2 = (const float*)d_in[13];
    const float* b2 = (const float*)d_in[14];
    const float* ln2_g = (const float*)d_in[15];
    const float* ln2_b = (const float*)d_in[16];
    float* out = (float*)d_out;

    bf16 *hh, *hl, *qh, *ql, *kh, *kl, *vh, *vl, *ath, *atl, *h2h, *h2l, *ffh, *ffl;
    bf16 *wqh, *wql, *wkh, *wkl, *wvh, *wvl, *woh, *wol, *w1h, *w1l, *w2h, *w2l;
    float *x1;
    cudaGetSymbolAddress((void**)&hh,  g_hh);  cudaGetSymbolAddress((void**)&hl,  g_hl);
    cudaGetSymbolAddress((void**)&qh,  g_qh);  cudaGetSymbolAddress((void**)&ql,  g_ql);
    cudaGetSymbolAddress((void**)&kh,  g_kh);  cudaGetSymbolAddress((void**)&kl,  g_kl);
    cudaGetSymbolAddress((void**)&vh,  g_vh);  cudaGetSymbolAddress((void**)&vl,  g_vl);
    cudaGetSymbolAddress((void**)&ath, g_ath); cudaGetSymbolAddress((void**)&atl, g_atl);
    cudaGetSymbolAddress((void**)&x1,  g_x1);
    cudaGetSymbolAddress((void**)&h2h, g_h2h); cudaGetSymbolAddress((void**)&h2l, g_h2l);
    cudaGetSymbolAddress((void**)&ffh, g_ffh); cudaGetSymbolAddress((void**)&ffl, g_ffl);
    cudaGetSymbolAddress((void**)&wqh, g_wqh); cudaGetSymbolAddress((void**)&wql, g_wql);
    cudaGetSymbolAddress((void**)&wkh, g_wkh); cudaGetSymbolAddress((void**)&wkl, g_wkl);
    cudaGetSymbolAddress((void**)&wvh, g_wvh); cudaGetSymbolAddress((void**)&wvl, g_wvl);
    cudaGetSymbolAddress((void**)&woh, g_woh); cudaGetSymbolAddress((void**)&wol, g_wol);
    cudaGetSymbolAddress((void**)&w1h, g_w1h); cudaGetSymbolAddress((void**)&w1l, g_w1l);
    cudaGetSymbolAddress((void**)&w2h, g_w2h); cudaGetSymbolAddress((void**)&w2l, g_w2l);

    cudaFuncSetAttribute(mm_tc<0>, cudaFuncAttributeMaxDynamicSharedMemorySize, MM_SMEM);
    cudaFuncSetAttribute(mm_tc<1>, cudaFuncAttributeMaxDynamicSharedMemorySize, MM_SMEM);
    cudaFuncSetAttribute(mm_tc<2>, cudaFuncAttributeMaxDynamicSharedMemorySize, MM_SMEM);
    cudaFuncSetAttribute(mm_tc<3>, cudaFuncAttributeMaxDynamicSharedMemorySize, MM_SMEM);
    cudaFuncSetAttribute(attn_tc,  cudaFuncAttributeMaxDynamicSharedMemorySize, ASMEM);

    // weight transpose + split
    wsplit<<<dim3(DIM/32, DIM/32), 256>>>(wq, wqh, wql, DIM, DIM);
    wsplit<<<dim3(DIM/32, DIM/32), 256>>>(wk, wkh, wkl, DIM, DIM);
    wsplit<<<dim3(DIM/32, DIM/32), 256>>>(wv, wvh, wvl, DIM, DIM);
    wsplit<<<dim3(DIM/32, DIM/32), 256>>>(wo, woh, wol, DIM, DIM);
    wsplit<<<dim3(DFF/32, DIM/32), 256>>>(w1, w1h, w1l, DIM, DFF);
    wsplit<<<dim3(DIM/32, DFF/32), 256>>>(w2, w2h, w2l, DFF, DIM);

    const dim3 gD(DIM / 128, TOK / 128);
    const dim3 gF(DFF / 128, TOK / 128);

    ln_split<<<TOK, 256>>>(x, ln1_g, ln1_b, hh, hl);
    mm_tc<3><<<gD, 256, MM_SMEM>>>(hh, hl, wqh, wql, bq, nullptr, nullptr, qh, ql, TOK, DIM, DIM, 0.125f);
    mm_tc<3><<<gD, 256, MM_SMEM>>>(hh, hl, wkh, wkl, bk, nullptr, nullptr, kh, kl, TOK, DIM, DIM, 1.0f);
    mm_tc<3><<<gD, 256, MM_SMEM>>>(hh, hl, wvh, wvl, bv, nullptr, nullptr, vh, vl, TOK, DIM, DIM, 1.0f);
    attn_tc<<<dim3(SEQ / 128, BATCH * NH), 256, ASMEM>>>(qh, ql, kh, kl, vh, vl, ath, atl);
    mm_tc<1><<<gD, 256, MM_SMEM>>>(ath, atl, woh, wol, bo, x, x1, nullptr, nullptr, TOK, DIM, DIM, 1.0f);
    ln_split<<<TOK, 256>>>(x1, ln2_g, ln2_b, h2h, h2l);
    mm_tc<2><<<gF, 256, MM_SMEM>>>(h2h, h2l, w1h, w1l, b1, nullptr, nullptr, ffh, ffl, TOK, DFF, DIM, 1.0f);
    mm_tc<1><<<gD, 256, MM_SMEM>>>(ffh, ffl, w2h, w2l, b2, x1, out, nullptr, nullptr, TOK, DIM, DFF, 1.0f);
}

// round 12
// speedup vs baseline: 1.0822x; 1.0822x over previous
#include <cuda_runtime.h>
#include <cuda_bf16.h>
#include <math.h>
#include <cstdint>

// ---------------------------------------------------------------------------
// Encoder_84413287236054 : fp32 transformer encoder layer on GB300
// Round 12: revert mm_tc to R10 staging; merge QKV into one launch;
// attention v4: 4 warps x 32 q-rows (halved LDSM/MMA ratio), cp.async K/V.
// ---------------------------------------------------------------------------

#define TOK  4096
#define DIM  1024
#define DFF  4096
#define NH   16
#define HD   64
#define SEQ  2048
#define BATCH 2

typedef unsigned long long u64;
typedef __nv_bfloat16 bf16;

// ---- tensor-core primitives (compute_103-legal) ----------------------------
__device__ __forceinline__ uint32_t smem_u32(const void* p) {
    uint32_t a;
    asm("{ .reg .u64 t; cvta.to.shared.u64 t, %1; cvt.u32.u64 %0, t; }" : "=r"(a) : "l"(p));
    return a;
}
__device__ __forceinline__ void ldmx4(uint32_t* r, uint32_t addr) {
    asm volatile("ldmatrix.sync.aligned.m8n8.x4.shared.b16 {%0,%1,%2,%3},[%4];"
        : "=r"(r[0]), "=r"(r[1]), "=r"(r[2]), "=r"(r[3]) : "r"(addr));
}
__device__ __forceinline__ void ldmx4t(uint32_t* r, uint32_t addr) {
    asm volatile("ldmatrix.sync.aligned.m8n8.x4.trans.shared.b16 {%0,%1,%2,%3},[%4];"
        : "=r"(r[0]), "=r"(r[1]), "=r"(r[2]), "=r"(r[3]) : "r"(addr));
}
__device__ __forceinline__ void mma_bf16(float* c, const uint32_t* a, const uint32_t* b) {
    asm volatile("mma.sync.aligned.m16n8k16.row.col.f32.bf16.bf16.f32 "
        "{%0,%1,%2,%3},{%4,%5,%6,%7},{%8,%9},{%0,%1,%2,%3};"
        : "+f"(c[0]), "+f"(c[1]), "+f"(c[2]), "+f"(c[3])
        : "r"(a[0]), "r"(a[1]), "r"(a[2]), "r"(a[3]), "r"(b[0]), "r"(b[1]));
}
__device__ __forceinline__ void cp16(uint32_t dst, const void* src) {
    asm volatile("cp.async.cg.shared.global [%0],[%1],16;" :: "r"(dst), "l"(src));
}
#define CP_COMMIT() asm volatile("cp.async.commit_group;" ::: "memory")
#define CP_WAIT0()  asm volatile("cp.async.wait_group 0;" ::: "memory")

__device__ __forceinline__ void split1(float x, bf16& h, bf16& l) {
    h = __float2bfloat16(x);
    l = __float2bfloat16(x - __bfloat162float(h));
}
__device__ __forceinline__ uint32_t packbf2(bf16 a, bf16 b) {
    __nv_bfloat162 t = __halves2bfloat162(a, b);
    return *(uint32_t*)&t;
}
__device__ __forceinline__ void split2pack(float a, float b, uint32_t& hp, uint32_t& lp) {
    bf16 ha, la, hb, lb;
    split1(a, ha, la); split1(b, hb, lb);
    hp = packbf2(ha, hb); lp = packbf2(la, lb);
}

// ---------------- scratch (allocation-free) ---------------------------------
__device__ bf16  g_hh [TOK * DIM], g_hl [TOK * DIM];
__device__ bf16  g_qh [TOK * DIM], g_ql [TOK * DIM];
__device__ bf16  g_kh [TOK * DIM], g_kl [TOK * DIM];
__device__ bf16  g_vh [TOK * DIM], g_vl [TOK * DIM];
__device__ bf16  g_ath[TOK * DIM], g_atl[TOK * DIM];
__device__ float g_x1 [TOK * DIM];
__device__ bf16  g_h2h[TOK * DIM], g_h2l[TOK * DIM];
__device__ bf16  g_ffh[TOK * DFF], g_ffl[TOK * DFF];
__device__ bf16 g_wqh[DIM * DIM], g_wql[DIM * DIM];
__device__ bf16 g_wkh[DIM * DIM], g_wkl[DIM * DIM];
__device__ bf16 g_wvh[DIM * DIM], g_wvl[DIM * DIM];
__device__ bf16 g_woh[DIM * DIM], g_wol[DIM * DIM];
__device__ bf16 g_w1h[DFF * DIM], g_w1l[DFF * DIM];
__device__ bf16 g_w2h[DIM * DFF], g_w2l[DIM * DFF];

// ---------------------------------------------------------------------------
// Weight transpose + hi/lo split: W[K,N] fp32 -> Th,Tl [N,K] bf16
// ---------------------------------------------------------------------------
__global__ __launch_bounds__(256) void wsplit(
    const float* __restrict__ W, bf16* __restrict__ Th, bf16* __restrict__ Tl,
    int K, int N)
{
    __shared__ float t[32][33];
    const int n0 = blockIdx.x * 32, k0 = blockIdx.y * 32;
    const int tx = threadIdx.x & 31, ty = threadIdx.x >> 5;
    #pragma unroll
    for (int i = ty; i < 32; i += 8)
        t[i][tx] = W[(size_t)(k0 + i) * N + n0 + tx];
    __syncthreads();
    #pragma unroll
    for (int i = ty; i < 32; i += 8) {
        const float x = t[tx][i];
        bf16 h, l; split1(x, h, l);
        Th[(size_t)(n0 + i) * K + k0 + tx] = h;
        Tl[(size_t)(n0 + i) * K + k0 + tx] = l;
    }
}

// ---------------------------------------------------------------------------
// LayerNorm -> bf16 hi/lo
// ---------------------------------------------------------------------------
__global__ __launch_bounds__(256) void ln_split(
    const float* __restrict__ x, const float* __restrict__ g,
    const float* __restrict__ b, bf16* __restrict__ oh, bf16* __restrict__ ol)
{
    const int row = blockIdx.x;
    const int t = threadIdx.x;
    const float4 v = ((const float4*)(x + (size_t)row * DIM))[t];

    float s  = v.x + v.y + v.z + v.w;
    float ss = v.x*v.x + v.y*v.y + v.z*v.z + v.w*v.w;
    #pragma unroll
    for (int o = 16; o; o >>= 1) {
        s  += __shfl_xor_sync(0xffffffffu, s,  o);
        ss += __shfl_xor_sync(0xffffffffu, ss, o);
    }
    __shared__ float sm[8], sm2[8];
    if ((t & 31) == 0) { sm[t >> 5] = s; sm2[t >> 5] = ss; }
    __syncthreads();
    float ts = 0.f, tss = 0.f;
    #pragma unroll
    for (int i = 0; i < 8; i++) { ts += sm[i]; tss += sm2[i]; }

    const float mu   = ts * (1.0f / DIM);
    const float rstd = rsqrtf(tss * (1.0f / DIM) - mu * mu + 1e-5f);
    const float4 gv = ((const float4*)g)[t];
    const float4 bv = ((const float4*)b)[t];
    float y[4];
    y[0] = (v.x - mu) * rstd * gv.x + bv.x;
    y[1] = (v.y - mu) * rstd * gv.y + bv.y;
    y[2] = (v.z - mu) * rstd * gv.z + bv.z;
    y[3] = (v.w - mu) * rstd * gv.w + bv.w;
    uint32_t hp0, lp0, hp1, lp1;
    split2pack(y[0], y[1], hp0, lp0);
    split2pack(y[2], y[3], hp1, lp1);
    *(uint2*)(oh + (size_t)row * DIM + t * 4) = make_uint2(hp0, hp1);
    *(uint2*)(ol + (size_t)row * DIM + t * 4) = make_uint2(lp0, lp1);
}

// ---------------------------------------------------------------------------
// Tensor-core GEMM (R10 staging: LDG register prefetch + STS burst)
// C[M,N] = (Ah+Al)[M,K] @ (Bh+Bl)^T   (B stored [N,K])
// ---------------------------------------------------------------------------
#define ARR_B  10240u
#define BUFSZ  40960u
#define MM_SMEM (2u * BUFSZ)

template<int EPI>
__global__ __launch_bounds__(256, 1) void mm_tc(
    const bf16* __restrict__ Ah, const bf16* __restrict__ Al,
    const bf16* __restrict__ Bh, const bf16* __restrict__ Bl,
    const float* __restrict__ bias, const float* __restrict__ res,
    float* __restrict__ C, bf16* __restrict__ Ch, bf16* __restrict__ Cl,
    int M, int N, int K, float oscale)
{
    extern __shared__ char smem[];
    const uint32_t sb = smem_u32(smem);
    const int tid = threadIdx.x, wid = tid >> 5, lid = tid & 31;
    const int wm = wid & 1, wn = wid >> 1;
    const int m0 = blockIdx.y * 128, n0 = blockIdx.x * 128;

    const int r0_ = tid >> 2, c0_ = tid & 3;
    const int r1_ = r0_ + 64;

    const bf16* srcs[4] = { Ah, Al, Bh, Bl };
    const int   base4[4] = { m0, m0, n0, n0 };

    auto fetch = [&](int kt, uint4* pf) {
        #pragma unroll
        for (int a = 0; a < 4; a++) {
            const bf16* s = srcs[a] + (size_t)base4[a] * K + kt * 32;
            pf[a * 2 + 0] = *(const uint4*)(s + (size_t)r0_ * K + c0_ * 8);
            pf[a * 2 + 1] = *(const uint4*)(s + (size_t)r1_ * K + c0_ * 8);
        }
    };
    auto commit = [&](int buf, const uint4* pf) {
        char* bb = smem + buf * BUFSZ;
        #pragma unroll
        for (int a = 0; a < 4; a++) {
            *(uint4*)(bb + a * ARR_B + r0_ * 80 + c0_ * 16) = pf[a * 2 + 0];
            *(uint4*)(bb + a * ARR_B + r1_ * 80 + c0_ * 16) = pf[a * 2 + 1];
        }
    };

    float acc[4][4][4] = {};

    const int arow = wm * 64 + (lid & 7) + ((lid >> 3) & 1) * 8;
    const uint32_t acolb = ((lid >> 4) & 1) * 16;
    const int brow = wn * 32 + (lid & 7) + ((lid >> 4) & 1) * 8;
    const uint32_t bcolb = ((lid >> 3) & 1) * 16;

    {
        uint4 pf[8];
        fetch(0, pf);
        commit(0, pf);
    }
    __syncthreads();

    const int nk = K >> 5;
    for (int kt = 0; kt < nk; kt++) {
        const int buf = kt & 1;
        uint4 pf[8];
        if (kt + 1 < nk) fetch(kt + 1, pf);

        const uint32_t bb = sb + buf * BUFSZ;
        #pragma unroll
        for (int kh = 0; kh < 2; kh++) {
            uint32_t ah[4][4], al[4][4], bh[4][2], bl[4][2];
            #pragma unroll
            for (int mf = 0; mf < 4; mf++) {
                const uint32_t ad = bb + (arow + mf * 16) * 80 + acolb + kh * 32;
                ldmx4(ah[mf], ad);
                ldmx4(al[mf], ad + ARR_B);
            }
            #pragma unroll
            for (int g2 = 0; g2 < 2; g2++) {
                const uint32_t bd = bb + 2 * ARR_B + (brow + g2 * 16) * 80 + bcolb + kh * 32;
                uint32_t t[4];
                ldmx4(t, bd);
                bh[g2*2][0] = t[0]; bh[g2*2][1] = t[1];
                bh[g2*2+1][0] = t[2]; bh[g2*2+1][1] = t[3];
                ldmx4(t, bd + ARR_B);
                bl[g2*2][0] = t[0]; bl[g2*2][1] = t[1];
                bl[g2*2+1][0] = t[2]; bl[g2*2+1][1] = t[3];
            }
            #pragma unroll
            for (int mf = 0; mf < 4; mf++)
                #pragma unroll
                for (int nf = 0; nf < 4; nf++) {
                    mma_bf16(acc[mf][nf], ah[mf], bh[nf]);
                    mma_bf16(acc[mf][nf], ah[mf], bl[nf]);
                    mma_bf16(acc[mf][nf], al[mf], bh[nf]);
                }
        }

        if (kt + 1 < nk) {
            commit(buf ^ 1, pf);
            __syncthreads();
        }
    }

    // ---------------- epilogue ----------------
    #pragma unroll
    for (int mf = 0; mf < 4; mf++) {
        const int rowA = m0 + wm * 64 + mf * 16 + (lid >> 2);
        const int rowB = rowA + 8;
        #pragma unroll
        for (int nf = 0; nf < 4; nf++) {
            const int col = n0 + wn * 32 + nf * 8 + (lid & 3) * 2;
            const float2 b2 = *(const float2*)(bias + col);
            float v0 = acc[mf][nf][0] + b2.x;
            float v1 = acc[mf][nf][1] + b2.y;
            float v2 = acc[mf][nf][2] + b2.x;
            float v3 = acc[mf][nf][3] + b2.y;
            const size_t offA = (size_t)rowA * N + col;
            const size_t offB = (size_t)rowB * N + col;
            if (EPI == 1) {
                const float2 rA = *(const float2*)(res + offA);
                const float2 rB = *(const float2*)(res + offB);
                v0 += rA.x; v1 += rA.y; v2 += rB.x; v3 += rB.y;
            }
            if (EPI == 2 || EPI == 3) {
                if (EPI == 2) {
                    v0 = v0 * normcdff(v0); v1 = v1 * normcdff(v1);
                    v2 = v2 * normcdff(v2); v3 = v3 * normcdff(v3);
                } else {
                    v0 *= oscale; v1 *= oscale; v2 *= oscale; v3 *= oscale;
                }
                uint32_t hA, lA, hB, lB;
                split2pack(v0, v1, hA, lA);
                split2pack(v2, v3, hB, lB);
                *(uint32_t*)(Ch + offA) = hA;
                *(uint32_t*)(Cl + offA) = lA;
                *(uint32_t*)(Ch + offB) = hB;
                *(uint32_t*)(Cl + offB) = lB;
            } else {
                *(float2*)(C + offA) = make_float2(v0, v1);
                *(float2*)(C + offB) = make_float2(v2, v3);
            }
        }
    }
}

// ---------------------------------------------------------------------------
// Merged QKV GEMM: grid.x = 24 (seg = x>>3 selects Q/K/V), grid.y = 32.
// Same body as mm_tc<3> with M=TOK, N=DIM, K=DIM.
// ---------------------------------------------------------------------------
__global__ __launch_bounds__(256, 1) void mm_qkv(
    const bf16* __restrict__ Ah, const bf16* __restrict__ Al,
    const bf16* __restrict__ B0h, const bf16* __restrict__ B0l,
    const bf16* __restrict__ B1h, const bf16* __restrict__ B1l,
    const bf16* __restrict__ B2h, const bf16* __restrict__ B2l,
    const float* __restrict__ bias0, const float* __restrict__ bias1,
    const float* __restrict__ bias2,
    bf16* __restrict__ C0h, bf16* __restrict__ C0l,
    bf16* __restrict__ C1h, bf16* __restrict__ C1l,
    bf16* __restrict__ C2h, bf16* __restrict__ C2l)
{
    extern __shared__ char smem[];
    const uint32_t sb = smem_u32(smem);
    const int tid = threadIdx.x, wid = tid >> 5, lid = tid & 31;
    const int wm = wid & 1, wn = wid >> 1;
    const int seg = blockIdx.x >> 3;
    const int m0 = blockIdx.y * 128, n0 = (blockIdx.x & 7) * 128;

    const bf16* Bh = (seg == 0) ? B0h : (seg == 1) ? B1h : B2h;
    const bf16* Bl = (seg == 0) ? B0l : (seg == 1) ? B1l : B2l;
    const float* bias = (seg == 0) ? bias0 : (seg == 1) ? bias1 : bias2;
    bf16* Ch = (seg == 0) ? C0h : (seg == 1) ? C1h : C2h;
    bf16* Cl = (seg == 0) ? C0l : (seg == 1) ? C1l : C2l;
    const float oscale = (seg == 0) ? 0.125f : 1.0f;

    const int r0_ = tid >> 2, c0_ = tid & 3;
    const int r1_ = r0_ + 64;

    const bf16* srcs[4] = { Ah, Al, Bh, Bl };
    const int   base4[4] = { m0, m0, n0, n0 };

    auto fetch = [&](int kt, uint4* pf) {
        #pragma unroll
        for (int a = 0; a < 4; a++) {
            const bf16* s = srcs[a] + (size_t)base4[a] * DIM + kt * 32;
            pf[a * 2 + 0] = *(const uint4*)(s + (size_t)r0_ * DIM + c0_ * 8);
            pf[a * 2 + 1] = *(const uint4*)(s + (size_t)r1_ * DIM + c0_ * 8);
        }
    };
    auto commit = [&](int buf, const uint4* pf) {
        char* bb = smem + buf * BUFSZ;
        #pragma unroll
        for (int a = 0; a < 4; a++) {
            *(uint4*)(bb + a * ARR_B + r0_ * 80 + c0_ * 16) = pf[a * 2 + 0];
            *(uint4*)(bb + a * ARR_B + r1_ * 80 + c0_ * 16) = pf[a * 2 + 1];
        }
    };

    float acc[4][4][4] = {};

    const int arow = wm * 64 + (lid & 7) + ((lid >> 3) & 1) * 8;
    const uint32_t acolb = ((lid >> 4) & 1) * 16;
    const int brow = wn * 32 + (lid & 7) + ((lid >> 4) & 1) * 8;
    const uint32_t bcolb = ((lid >> 3) & 1) * 16;

    {
        uint4 pf[8];
        fetch(0, pf);
        commit(0, pf);
    }
    __syncthreads();

    const int nk = DIM >> 5;
    for (int kt = 0; kt < nk; kt++) {
        const int buf = kt & 1;
        uint4 pf[8];
        if (kt + 1 < nk) fetch(kt + 1, pf);

        const uint32_t bb = sb + buf * BUFSZ;
        #pragma unroll
        for (int kh = 0; kh < 2; kh++) {
            uint32_t ah[4][4], al[4][4], bh[4][2], bl[4][2];
            #pragma unroll
            for (int mf = 0; mf < 4; mf++) {
                const uint32_t ad = bb + (arow + mf * 16) * 80 + acolb + kh * 32;
                ldmx4(ah[mf], ad);
                ldmx4(al[mf], ad + ARR_B);
            }
            #pragma unroll
            for (int g2 = 0; g2 < 2; g2++) {
                const uint32_t bd = bb + 2 * ARR_B + (brow + g2 * 16) * 80 + bcolb + kh * 32;
                uint32_t t[4];
                ldmx4(t, bd);
                bh[g2*2][0] = t[0]; bh[g2*2][1] = t[1];
                bh[g2*2+1][0] = t[2]; bh[g2*2+1][1] = t[3];
                ldmx4(t, bd + ARR_B);
                bl[g2*2][0] = t[0]; bl[g2*2][1] = t[1];
                bl[g2*2+1][0] = t[2]; bl[g2*2+1][1] = t[3];
            }
            #pragma unroll
            for (int mf = 0; mf < 4; mf++)
                #pragma unroll
                for (int nf = 0; nf < 4; nf++) {
                    mma_bf16(acc[mf][nf], ah[mf], bh[nf]);
                    mma_bf16(acc[mf][nf], ah[mf], bl[nf]);
                    mma_bf16(acc[mf][nf], al[mf], bh[nf]);
                }
        }

        if (kt + 1 < nk) {
            commit(buf ^ 1, pf);
            __syncthreads();
        }
    }

    #pragma unroll
    for (int mf = 0; mf < 4; mf++) {
        const int rowA = m0 + wm * 64 + mf * 16 + (lid >> 2);
        const int rowB = rowA + 8;
        #pragma unroll
        for (int nf = 0; nf < 4; nf++) {
            const int col = n0 + wn * 32 + nf * 8 + (lid & 3) * 2;
            const float2 b2 = *(const float2*)(bias + col);
            float v0 = (acc[mf][nf][0] + b2.x) * oscale;
            float v1 = (acc[mf][nf][1] + b2.y) * oscale;
            float v2 = (acc[mf][nf][2] + b2.x) * oscale;
            float v3 = (acc[mf][nf][3] + b2.y) * oscale;
            const size_t offA = (size_t)rowA * DIM + col;
            const size_t offB = (size_t)rowB * DIM + col;
            uint32_t hA, lA, hB, lB;
            split2pack(v0, v1, hA, lA);
            split2pack(v2, v3, hB, lB);
            *(uint32_t*)(Ch + offA) = hA;
            *(uint32_t*)(Cl + offA) = lA;
            *(uint32_t*)(Ch + offB) = hB;
            *(uint32_t*)(Cl + offB) = lB;
        }
    }
}

// ---------------------------------------------------------------------------
// Flash attention v4. Grid (SEQ/128, B*NH). Block 128 = 4 warps; warp = 32 q
// (two m16 A-tiles) -> B-fragment ldmatrix amortized over 2x MMAs.
// Qh fragments resident; Ql re-loaded from smem per k-step. cp.async K/V.
// ---------------------------------------------------------------------------
#define AQ_B   18432u                   // 128 * 144
#define AKV_B  9216u                    // 64 * 144
#define KV0    (2u * AQ_B)
#define KVBUF  (4u * AKV_B)
#define ASMEM  (KV0 + 2u * KVBUF)       // 110592

__global__ __launch_bounds__(128, 2) void attn_tc(
    const bf16* __restrict__ qh, const bf16* __restrict__ ql,
    const bf16* __restrict__ kh, const bf16* __restrict__ kl,
    const bf16* __restrict__ vh, const bf16* __restrict__ vl,
    bf16* __restrict__ oh, bf16* __restrict__ ol)
{
    extern __shared__ char smem[];
    const uint32_t sb = smem_u32(smem);
    const int tid = threadIdx.x, wid = tid >> 5, lid = tid & 31;
    const int bh_ = blockIdx.y;
    const int b = bh_ >> 4, h = bh_ & 15;
    const int q0 = blockIdx.x * 128;
    const size_t base = (size_t)(b * SEQ) * DIM + h * HD;

    // cp.async a 64-row K/V tile into buffer (16 x 16B per thread)
    auto cpKV = [&](int kt, int buf) {
        const size_t rowb = base + (size_t)(kt * 64) * DIM;
        const uint32_t bb = sb + KV0 + buf * KVBUF;
        #pragma unroll
        for (int u = 0; u < 4; u++) {
            const int idx = u * 128 + tid;          // 0..511
            const int r = idx >> 3, c8 = idx & 7;
            const size_t gp = rowb + (size_t)r * DIM + c8 * 8;
            const uint32_t so = r * 144 + c8 * 16;
            cp16(bb + 0*AKV_B + so, kh + gp);
            cp16(bb + 1*AKV_B + so, kl + gp);
            cp16(bb + 2*AKV_B + so, vh + gp);
            cp16(bb + 3*AKV_B + so, vl + gp);
        }
        CP_COMMIT();
    };

    // ---- first K/V tile + stage Q tile (128 rows hi/lo) ----
    cpKV(0, 0);
    #pragma unroll
    for (int it = 0; it < 8; it++) {
        const int idx = it * 128 + tid;             // 0..1023
        const int r = idx >> 3, c8 = idx & 7;
        const size_t gp = base + (size_t)(q0 + r) * DIM + c8 * 8;
        *(uint4*)(smem + 0    + r * 144 + c8 * 16) = *(const uint4*)(qh + gp);
        *(uint4*)(smem + AQ_B + r * 144 + c8 * 16) = *(const uint4*)(ql + gp);
    }
    CP_WAIT0();
    __syncthreads();

    // ---- resident Qh A-fragments (2 m-tiles x 4 k-steps) ----
    const int arowb = wid * 32 + (lid & 7) + ((lid >> 3) & 1) * 8;
    const uint32_t acol = ((lid >> 4) & 1) * 16;
    uint32_t Qh_[2][4][4];
    #pragma unroll
    for (int mt = 0; mt < 2; mt++)
        #pragma unroll
        for (int ks = 0; ks < 4; ks++)
            ldmx4(Qh_[mt][ks], sb + (arowb + mt * 16) * 144 + acol + ks * 32);

    float O[2][8][4] = {};
    float m_[2][2] = { {-1e30f, -1e30f}, {-1e30f, -1e30f} };
    float l_[2][2] = { {0.f, 0.f}, {0.f, 0.f} };

    const int brow = (lid & 7) + ((lid >> 4) & 1) * 8;
    const uint32_t bcol = ((lid >> 3) & 1) * 16;
    const int vrow = (lid & 7) + ((lid >> 3) & 1) * 8;
    const uint32_t vcole = ((lid >> 4) & 1) * 8;

    const int NT = SEQ / 64;
    for (int kt = 0; kt < NT; kt++) {
        const int buf = kt & 1;
        if (kt + 1 < NT) cpKV(kt + 1, buf ^ 1);

        const uint32_t kvb = sb + KV0 + buf * KVBUF;

        // ---- scores S = Q K^T (3-MMA hi/lo), Ql re-loaded per k-step ----
        float S[2][8][4] = {};
        #pragma unroll
        for (int ks = 0; ks < 4; ks++) {
            uint32_t qlf[2][4];
            #pragma unroll
            for (int mt = 0; mt < 2; mt++)
                ldmx4(qlf[mt], sb + AQ_B + (arowb + mt * 16) * 144 + acol + ks * 32);
            #pragma unroll
            for (int g2 = 0; g2 < 4; g2++) {
                const uint32_t bd = kvb + (brow + g2 * 16) * 144 + bcol + ks * 32;
                uint32_t th[4], tl[4];
                ldmx4(th, bd);
                ldmx4(tl, bd + AKV_B);
                uint32_t bh0[2] = { th[0], th[1] }, bh1[2] = { th[2], th[3] };
                uint32_t bl0[2] = { tl[0], tl[1] }, bl1[2] = { tl[2], tl[3] };
                #pragma unroll
                for (int mt = 0; mt < 2; mt++) {
                    mma_bf16(S[mt][g2*2],   Qh_[mt][ks], bh0);
                    mma_bf16(S[mt][g2*2],   Qh_[mt][ks], bl0);
                    mma_bf16(S[mt][g2*2],   qlf[mt],     bh0);
                    mma_bf16(S[mt][g2*2+1], Qh_[mt][ks], bh1);
                    mma_bf16(S[mt][g2*2+1], Qh_[mt][ks], bl1);
                    mma_bf16(S[mt][g2*2+1], qlf[mt],     bh1);
                }
            }
        }

        // ---- online softmax (per m-tile) ----
        #pragma unroll
        for (int mt = 0; mt < 2; mt++) {
            float rm0 = -1e30f, rm1 = -1e30f;
            #pragma unroll
            for (int nf = 0; nf < 8; nf++) {
                rm0 = fmaxf(rm0, fmaxf(S[mt][nf][0], S[mt][nf][1]));
                rm1 = fmaxf(rm1, fmaxf(S[mt][nf][2], S[mt][nf][3]));
            }
            rm0 = fmaxf(rm0, __shfl_xor_sync(0xffffffffu, rm0, 1));
            rm0 = fmaxf(rm0, __shfl_xor_sync(0xffffffffu, rm0, 2));
            rm1 = fmaxf(rm1, __shfl_xor_sync(0xffffffffu, rm1, 1));
            rm1 = fmaxf(rm1, __shfl_xor_sync(0xffffffffu, rm1, 2));
            const float mn0 = fmaxf(m_[mt][0], rm0), mn1 = fmaxf(m_[mt][1], rm1);
            const float c0 = __expf(m_[mt][0] - mn0), c1 = __expf(m_[mt][1] - mn1);
            m_[mt][0] = mn0; m_[mt][1] = mn1;

            float rs0 = 0.f, rs1 = 0.f;
            #pragma unroll
            for (int nf = 0; nf < 8; nf++) {
                S[mt][nf][0] = __expf(S[mt][nf][0] - mn0);
                S[mt][nf][1] = __expf(S[mt][nf][1] - mn0);
                S[mt][nf][2] = __expf(S[mt][nf][2] - mn1);
                S[mt][nf][3] = __expf(S[mt][nf][3] - mn1);
                rs0 += S[mt][nf][0] + S[mt][nf][1];
                rs1 += S[mt][nf][2] + S[mt][nf][3];
            }
            rs0 += __shfl_xor_sync(0xffffffffu, rs0, 1);
            rs0 += __shfl_xor_sync(0xffffffffu, rs0, 2);
            rs1 += __shfl_xor_sync(0xffffffffu, rs1, 1);
            rs1 += __shfl_xor_sync(0xffffffffu, rs1, 2);
            l_[mt][0] = l_[mt][0] * c0 + rs0;
            l_[mt][1] = l_[mt][1] * c1 + rs1;
            #pragma unroll
            for (int nf = 0; nf < 8; nf++) {
                O[mt][nf][0] *= c0; O[mt][nf][1] *= c0;
                O[mt][nf][2] *= c1; O[mt][nf][3] *= c1;
            }
        }

        // ---- P fragments (hi/lo) from S ----
        uint32_t Ph[2][4][4], Pl[2][4][4];
        #pragma unroll
        for (int mt = 0; mt < 2; mt++)
            #pragma unroll
            for (int t = 0; t < 4; t++) {
                split2pack(S[mt][2*t][0],   S[mt][2*t][1],   Ph[mt][t][0], Pl[mt][t][0]);
                split2pack(S[mt][2*t][2],   S[mt][2*t][3],   Ph[mt][t][1], Pl[mt][t][1]);
                split2pack(S[mt][2*t+1][0], S[mt][2*t+1][1], Ph[mt][t][2], Pl[mt][t][2]);
                split2pack(S[mt][2*t+1][2], S[mt][2*t+1][3], Ph[mt][t][3], Pl[mt][t][3]);
            }

        // ---- O += P V (3-MMA hi/lo), V row-major via ldmatrix.trans ----
        #pragma unroll
        for (int t = 0; t < 4; t++) {
            #pragma unroll
            for (int g2 = 0; g2 < 4; g2++) {
                const uint32_t vd = kvb + 2*AKV_B +
                    (t * 16 + vrow) * 144 + (g2 * 16 + vcole) * 2;
                uint32_t th[4], tl[4];
                ldmx4t(th, vd);
                ldmx4t(tl, vd + AKV_B);
                uint32_t bh0[2] = { th[0], th[1] }, bh1[2] = { th[2], th[3] };
                uint32_t bl0[2] = { tl[0], tl[1] }, bl1[2] = { tl[2], tl[3] };
                #pragma unroll
                for (int mt = 0; mt < 2; mt++) {
                    mma_bf16(O[mt][g2*2],   Ph[mt][t], bh0);
                    mma_bf16(O[mt][g2*2],   Pl[mt][t], bh0);
                    mma_bf16(O[mt][g2*2],   Ph[mt][t], bl0);
                    mma_bf16(O[mt][g2*2+1], Ph[mt][t], bh1);
                    mma_bf16(O[mt][g2*2+1], Pl[mt][t], bh1);
                    mma_bf16(O[mt][g2*2+1], Ph[mt][t], bl1);
                }
            }
        }

        if (kt + 1 < NT) {
            CP_WAIT0();
            __syncthreads();
        }
    }

    // ---- epilogue: normalize + bf16 hi/lo store ----
    #pragma unroll
    for (int mt = 0; mt < 2; mt++) {
        const float inv0 = 1.f / l_[mt][0], inv1 = 1.f / l_[mt][1];
        const int rowA = q0 + wid * 32 + mt * 16 + (lid >> 2);
        const int rowB = rowA + 8;
        #pragma unroll
        for (int nf = 0; nf < 8; nf++) {
            const int col = h * HD + nf * 8 + (lid & 3) * 2;
            const size_t offA = (size_t)(b * SEQ + rowA) * DIM + col;
            const size_t offB = (size_t)(b * SEQ + rowB) * DIM + col;
            uint32_t hA, lA, hB, lB;
            split2pack(O[mt][nf][0] * inv0, O[mt][nf][1] * inv0, hA, lA);
            split2pack(O[mt][nf][2] * inv1, O[mt][nf][3] * inv1, hB, lB);
            *(uint32_t*)(oh + offA) = hA;
            *(uint32_t*)(ol + offA) = lA;
            *(uint32_t*)(oh + offB) = hB;
            *(uint32_t*)(ol + offB) = lB;
        }
    }
}

// ---------------------------------------------------------------------------
extern "C" void kernel_launch(void* const* d_in, const int* in_sizes, int n_in,
                              void* d_out, int out_size)
{
    const float* x     = (const float*)d_in[0];
    const float* ln1_g = (const float*)d_in[1];
    const float* ln1_b = (const float*)d_in[2];
    const float* wq = (const float*)d_in[3];
    const float* bq = (const float*)d_in[4];
    const float* wk = (const float*)d_in[5];
    const float* bk = (const float*)d_in[6];
    const float* wv = (const float*)d_in[7];
    const float* bv = (const float*)d_in[8];
    const float* wo = (const float*)d_in[9];
    const float* bo = (const float*)d_in[10];
    const float* w1 = (const float*)d_in[11];
    const float* b1 = (const float*)d_in[12];
    const float* w2 = (const float*)d_in[13];
    const float* b2 = (const float*)d_in[14];
    const float* ln2_g = (const float*)d_in[15];
    const float* ln2_b = (const float*)d_in[16];
    float* out = (float*)d_out;

    bf16 *hh, *hl, *qh, *ql, *kh, *kl, *vh, *vl, *ath, *atl, *h2h, *h2l, *ffh, *ffl;
    bf16 *wqh, *wql, *wkh, *wkl, *wvh, *wvl, *woh, *wol, *w1h, *w1l, *w2h, *w2l;
    float *x1;
    cudaGetSymbolAddress((void**)&hh,  g_hh);  cudaGetSymbolAddress((void**)&hl,  g_hl);
    cudaGetSymbolAddress((void**)&qh,  g_qh);  cudaGetSymbolAddress((void**)&ql,  g_ql);
    cudaGetSymbolAddress((void**)&kh,  g_kh);  cudaGetSymbolAddress((void**)&kl,  g_kl);
    cudaGetSymbolAddress((void**)&vh,  g_vh);  cudaGetSymbolAddress((void**)&vl,  g_vl);
    cudaGetSymbolAddress((void**)&ath, g_ath); cudaGetSymbolAddress((void**)&atl, g_atl);
    cudaGetSymbolAddress((void**)&x1,  g_x1);
    cudaGetSymbolAddress((void**)&h2h, g_h2h); cudaGetSymbolAddress((void**)&h2l, g_h2l);
    cudaGetSymbolAddress((void**)&ffh, g_ffh); cudaGetSymbolAddress((void**)&ffl, g_ffl);
    cudaGetSymbolAddress((void**)&wqh, g_wqh); cudaGetSymbolAddress((void**)&wql, g_wql);
    cudaGetSymbolAddress((void**)&wkh, g_wkh); cudaGetSymbolAddress((void**)&wkl, g_wkl);
    cudaGetSymbolAddress((void**)&wvh, g_wvh); cudaGetSymbolAddress((void**)&wvl, g_wvl);
    cudaGetSymbolAddress((void**)&woh, g_woh); cudaGetSymbolAddress((void**)&wol, g_wol);
    cudaGetSymbolAddress((void**)&w1h, g_w1h); cudaGetSymbolAddress((void**)&w1l, g_w1l);
    cudaGetSymbolAddress((void**)&w2h, g_w2h); cudaGetSymbolAddress((void**)&w2l, g_w2l);

    cudaFuncSetAttribute(mm_tc<1>, cudaFuncAttributeMaxDynamicSharedMemorySize, MM_SMEM);
    cudaFuncSetAttribute(mm_tc<2>, cudaFuncAttributeMaxDynamicSharedMemorySize, MM_SMEM);
    cudaFuncSetAttribute(mm_qkv,   cudaFuncAttributeMaxDynamicSharedMemorySize, MM_SMEM);
    cudaFuncSetAttribute(attn_tc,  cudaFuncAttributeMaxDynamicSharedMemorySize, ASMEM);

    // weight transpose + split
    wsplit<<<dim3(DIM/32, DIM/32), 256>>>(wq, wqh, wql, DIM, DIM);
    wsplit<<<dim3(DIM/32, DIM/32), 256>>>(wk, wkh, wkl, DIM, DIM);
    wsplit<<<dim3(DIM/32, DIM/32), 256>>>(wv, wvh, wvl, DIM, DIM);
    wsplit<<<dim3(DIM/32, DIM/32), 256>>>(wo, woh, wol, DIM, DIM);
    wsplit<<<dim3(DFF/32, DIM/32), 256>>>(w1, w1h, w1l, DIM, DFF);
    wsplit<<<dim3(DIM/32, DFF/32), 256>>>(w2, w2h, w2l, DFF, DIM);

    const dim3 gD(DIM / 128, TOK / 128);
    const dim3 gF(DFF / 128, TOK / 128);

    ln_split<<<TOK, 256>>>(x, ln1_g, ln1_b, hh, hl);
    mm_qkv<<<dim3(24, TOK / 128), 256, MM_SMEM>>>(
        hh, hl, wqh, wql, wkh, wkl, wvh, wvl, bq, bk, bv,
        qh, ql, kh, kl, vh, vl);
    attn_tc<<<dim3(SEQ / 128, BATCH * NH), 128, ASMEM>>>(qh, ql, kh, kl, vh, vl, ath, atl);
    mm_tc<1><<<gD, 256, MM_SMEM>>>(ath, atl, woh, wol, bo, x, x1, nullptr, nullptr, TOK, DIM, DIM, 1.0f);
    ln_split<<<TOK, 256>>>(x1, ln2_g, ln2_b, h2h, h2l);
    mm_tc<2><<<gF, 256, MM_SMEM>>>(h2h, h2l, w1h, w1l, b1, nullptr, nullptr, ffh, ffl, TOK, DFF, DIM, 1.0f);
    mm_tc<1><<<gD, 256, MM_SMEM>>>(ffh, ffl, w2h, w2l, b2, x1, out, nullptr, nullptr, TOK, DIM, DFF, 1.0f);
}

// round 13
// speedup vs baseline: 1.1573x; 1.0695x over previous
#include <cuda_runtime.h>
#include <cuda_bf16.h>
#include <math.h>
#include <cstdint>

// ---------------------------------------------------------------------------
// Encoder_84413287236054 : fp32 transformer encoder layer on GB300
// Round 13: GEMMs switch to cp.async staging + 2 CTAs/SM (occupancy cover
// for latency + wave-quantization). Attention unchanged from R12 WIN.
// ---------------------------------------------------------------------------

#define TOK  4096
#define DIM  1024
#define DFF  4096
#define NH   16
#define HD   64
#define SEQ  2048
#define BATCH 2

typedef unsigned long long u64;
typedef __nv_bfloat16 bf16;

// ---- tensor-core primitives (compute_103-legal) ----------------------------
__device__ __forceinline__ uint32_t smem_u32(const void* p) {
    uint32_t a;
    asm("{ .reg .u64 t; cvta.to.shared.u64 t, %1; cvt.u32.u64 %0, t; }" : "=r"(a) : "l"(p));
    return a;
}
__device__ __forceinline__ void ldmx4(uint32_t* r, uint32_t addr) {
    asm volatile("ldmatrix.sync.aligned.m8n8.x4.shared.b16 {%0,%1,%2,%3},[%4];"
        : "=r"(r[0]), "=r"(r[1]), "=r"(r[2]), "=r"(r[3]) : "r"(addr));
}
__device__ __forceinline__ void ldmx4t(uint32_t* r, uint32_t addr) {
    asm volatile("ldmatrix.sync.aligned.m8n8.x4.trans.shared.b16 {%0,%1,%2,%3},[%4];"
        : "=r"(r[0]), "=r"(r[1]), "=r"(r[2]), "=r"(r[3]) : "r"(addr));
}
__device__ __forceinline__ void mma_bf16(float* c, const uint32_t* a, const uint32_t* b) {
    asm volatile("mma.sync.aligned.m16n8k16.row.col.f32.bf16.bf16.f32 "
        "{%0,%1,%2,%3},{%4,%5,%6,%7},{%8,%9},{%0,%1,%2,%3};"
        : "+f"(c[0]), "+f"(c[1]), "+f"(c[2]), "+f"(c[3])
        : "r"(a[0]), "r"(a[1]), "r"(a[2]), "r"(a[3]), "r"(b[0]), "r"(b[1]));
}
__device__ __forceinline__ void cp16(uint32_t dst, const void* src) {
    asm volatile("cp.async.cg.shared.global [%0],[%1],16;" :: "r"(dst), "l"(src));
}
#define CP_COMMIT() asm volatile("cp.async.commit_group;" ::: "memory")
#define CP_WAIT0()  asm volatile("cp.async.wait_group 0;" ::: "memory")

__device__ __forceinline__ void split1(float x, bf16& h, bf16& l) {
    h = __float2bfloat16(x);
    l = __float2bfloat16(x - __bfloat162float(h));
}
__device__ __forceinline__ uint32_t packbf2(bf16 a, bf16 b) {
    __nv_bfloat162 t = __halves2bfloat162(a, b);
    return *(uint32_t*)&t;
}
__device__ __forceinline__ void split2pack(float a, float b, uint32_t& hp, uint32_t& lp) {
    bf16 ha, la, hb, lb;
    split1(a, ha, la); split1(b, hb, lb);
    hp = packbf2(ha, hb); lp = packbf2(la, lb);
}

// ---------------- scratch (allocation-free) ---------------------------------
__device__ bf16  g_hh [TOK * DIM], g_hl [TOK * DIM];
__device__ bf16  g_qh [TOK * DIM], g_ql [TOK * DIM];
__device__ bf16  g_kh [TOK * DIM], g_kl [TOK * DIM];
__device__ bf16  g_vh [TOK * DIM], g_vl [TOK * DIM];
__device__ bf16  g_ath[TOK * DIM], g_atl[TOK * DIM];
__device__ float g_x1 [TOK * DIM];
__device__ bf16  g_h2h[TOK * DIM], g_h2l[TOK * DIM];
__device__ bf16  g_ffh[TOK * DFF], g_ffl[TOK * DFF];
__device__ bf16 g_wqh[DIM * DIM], g_wql[DIM * DIM];
__device__ bf16 g_wkh[DIM * DIM], g_wkl[DIM * DIM];
__device__ bf16 g_wvh[DIM * DIM], g_wvl[DIM * DIM];
__device__ bf16 g_woh[DIM * DIM], g_wol[DIM * DIM];
__device__ bf16 g_w1h[DFF * DIM], g_w1l[DFF * DIM];
__device__ bf16 g_w2h[DIM * DFF], g_w2l[DIM * DFF];

// ---------------------------------------------------------------------------
// Weight transpose + hi/lo split: W[K,N] fp32 -> Th,Tl [N,K] bf16
// ---------------------------------------------------------------------------
__global__ __launch_bounds__(256) void wsplit(
    const float* __restrict__ W, bf16* __restrict__ Th, bf16* __restrict__ Tl,
    int K, int N)
{
    __shared__ float t[32][33];
    const int n0 = blockIdx.x * 32, k0 = blockIdx.y * 32;
    const int tx = threadIdx.x & 31, ty = threadIdx.x >> 5;
    #pragma unroll
    for (int i = ty; i < 32; i += 8)
        t[i][tx] = W[(size_t)(k0 + i) * N + n0 + tx];
    __syncthreads();
    #pragma unroll
    for (int i = ty; i < 32; i += 8) {
        const float x = t[tx][i];
        bf16 h, l; split1(x, h, l);
        Th[(size_t)(n0 + i) * K + k0 + tx] = h;
        Tl[(size_t)(n0 + i) * K + k0 + tx] = l;
    }
}

// ---------------------------------------------------------------------------
// LayerNorm -> bf16 hi/lo
// ---------------------------------------------------------------------------
__global__ __launch_bounds__(256) void ln_split(
    const float* __restrict__ x, const float* __restrict__ g,
    const float* __restrict__ b, bf16* __restrict__ oh, bf16* __restrict__ ol)
{
    const int row = blockIdx.x;
    const int t = threadIdx.x;
    const float4 v = ((const float4*)(x + (size_t)row * DIM))[t];

    float s  = v.x + v.y + v.z + v.w;
    float ss = v.x*v.x + v.y*v.y + v.z*v.z + v.w*v.w;
    #pragma unroll
    for (int o = 16; o; o >>= 1) {
        s  += __shfl_xor_sync(0xffffffffu, s,  o);
        ss += __shfl_xor_sync(0xffffffffu, ss, o);
    }
    __shared__ float sm[8], sm2[8];
    if ((t & 31) == 0) { sm[t >> 5] = s; sm2[t >> 5] = ss; }
    __syncthreads();
    float ts = 0.f, tss = 0.f;
    #pragma unroll
    for (int i = 0; i < 8; i++) { ts += sm[i]; tss += sm2[i]; }

    const float mu   = ts * (1.0f / DIM);
    const float rstd = rsqrtf(tss * (1.0f / DIM) - mu * mu + 1e-5f);
    const float4 gv = ((const float4*)g)[t];
    const float4 bv = ((const float4*)b)[t];
    float y[4];
    y[0] = (v.x - mu) * rstd * gv.x + bv.x;
    y[1] = (v.y - mu) * rstd * gv.y + bv.y;
    y[2] = (v.z - mu) * rstd * gv.z + bv.z;
    y[3] = (v.w - mu) * rstd * gv.w + bv.w;
    uint32_t hp0, lp0, hp1, lp1;
    split2pack(y[0], y[1], hp0, lp0);
    split2pack(y[2], y[3], hp1, lp1);
    *(uint2*)(oh + (size_t)row * DIM + t * 4) = make_uint2(hp0, hp1);
    *(uint2*)(ol + (size_t)row * DIM + t * 4) = make_uint2(lp0, lp1);
}

// ---------------------------------------------------------------------------
// Tensor-core GEMM: cp.async staging, 2 CTAs/SM.
// C[M,N] = (Ah+Al)[M,K] @ (Bh+Bl)^T   (B stored [N,K])
// ---------------------------------------------------------------------------
#define ARR_B  10240u
#define BUFSZ  40960u
#define MM_SMEM (2u * BUFSZ)

template<int EPI>
__global__ __launch_bounds__(256, 2) void mm_tc(
    const bf16* __restrict__ Ah, const bf16* __restrict__ Al,
    const bf16* __restrict__ Bh, const bf16* __restrict__ Bl,
    const float* __restrict__ bias, const float* __restrict__ res,
    float* __restrict__ C, bf16* __restrict__ Ch, bf16* __restrict__ Cl,
    int M, int N, int K, float oscale)
{
    extern __shared__ char smem[];
    const uint32_t sb = smem_u32(smem);
    const int tid = threadIdx.x, wid = tid >> 5, lid = tid & 31;
    const int wm = wid & 1, wn = wid >> 1;
    const int m0 = blockIdx.y * 128, n0 = blockIdx.x * 128;

    const int r0_ = tid >> 2, c0_ = tid & 3;
    const int r1_ = r0_ + 64;

    const bf16* srcs[4] = { Ah, Al, Bh, Bl };
    const int   base4[4] = { m0, m0, n0, n0 };

    auto cpChunk = [&](int kt, int buf) {
        const uint32_t bb = sb + buf * BUFSZ;
        #pragma unroll
        for (int a = 0; a < 4; a++) {
            const bf16* s = srcs[a] + (size_t)base4[a] * K + kt * 32;
            cp16(bb + a * ARR_B + r0_ * 80 + c0_ * 16, s + (size_t)r0_ * K + c0_ * 8);
            cp16(bb + a * ARR_B + r1_ * 80 + c0_ * 16, s + (size_t)r1_ * K + c0_ * 8);
        }
        CP_COMMIT();
    };

    float acc[4][4][4] = {};

    const int arow = wm * 64 + (lid & 7) + ((lid >> 3) & 1) * 8;
    const uint32_t acolb = ((lid >> 4) & 1) * 16;
    const int brow = wn * 32 + (lid & 7) + ((lid >> 4) & 1) * 8;
    const uint32_t bcolb = ((lid >> 3) & 1) * 16;

    cpChunk(0, 0);
    CP_WAIT0();
    __syncthreads();

    const int nk = K >> 5;
    for (int kt = 0; kt < nk; kt++) {
        const int buf = kt & 1;
        if (kt + 1 < nk) cpChunk(kt + 1, buf ^ 1);

        const uint32_t bb = sb + buf * BUFSZ;
        #pragma unroll
        for (int kh = 0; kh < 2; kh++) {
            uint32_t ah[4][4], al[4][4], bh[4][2], bl[4][2];
            #pragma unroll
            for (int mf = 0; mf < 4; mf++) {
                const uint32_t ad = bb + (arow + mf * 16) * 80 + acolb + kh * 32;
                ldmx4(ah[mf], ad);
                ldmx4(al[mf], ad + ARR_B);
            }
            #pragma unroll
            for (int g2 = 0; g2 < 2; g2++) {
                const uint32_t bd = bb + 2 * ARR_B + (brow + g2 * 16) * 80 + bcolb + kh * 32;
                uint32_t t[4];
                ldmx4(t, bd);
                bh[g2*2][0] = t[0]; bh[g2*2][1] = t[1];
                bh[g2*2+1][0] = t[2]; bh[g2*2+1][1] = t[3];
                ldmx4(t, bd + ARR_B);
                bl[g2*2][0] = t[0]; bl[g2*2][1] = t[1];
                bl[g2*2+1][0] = t[2]; bl[g2*2+1][1] = t[3];
            }
            #pragma unroll
            for (int mf = 0; mf < 4; mf++)
                #pragma unroll
                for (int nf = 0; nf < 4; nf++) {
                    mma_bf16(acc[mf][nf], ah[mf], bh[nf]);
                    mma_bf16(acc[mf][nf], ah[mf], bl[nf]);
                    mma_bf16(acc[mf][nf], al[mf], bh[nf]);
                }
        }

        if (kt + 1 < nk) {
            CP_WAIT0();
            __syncthreads();
        }
    }

    // ---------------- epilogue ----------------
    #pragma unroll
    for (int mf = 0; mf < 4; mf++) {
        const int rowA = m0 + wm * 64 + mf * 16 + (lid >> 2);
        const int rowB = rowA + 8;
        #pragma unroll
        for (int nf = 0; nf < 4; nf++) {
            const int col = n0 + wn * 32 + nf * 8 + (lid & 3) * 2;
            const float2 b2 = *(const float2*)(bias + col);
            float v0 = acc[mf][nf][0] + b2.x;
            float v1 = acc[mf][nf][1] + b2.y;
            float v2 = acc[mf][nf][2] + b2.x;
            float v3 = acc[mf][nf][3] + b2.y;
            const size_t offA = (size_t)rowA * N + col;
            const size_t offB = (size_t)rowB * N + col;
            if (EPI == 1) {
                const float2 rA = *(const float2*)(res + offA);
                const float2 rB = *(const float2*)(res + offB);
                v0 += rA.x; v1 += rA.y; v2 += rB.x; v3 += rB.y;
            }
            if (EPI == 2 || EPI == 3) {
                if (EPI == 2) {
                    v0 = v0 * normcdff(v0); v1 = v1 * normcdff(v1);
                    v2 = v2 * normcdff(v2); v3 = v3 * normcdff(v3);
                } else {
                    v0 *= oscale; v1 *= oscale; v2 *= oscale; v3 *= oscale;
                }
                uint32_t hA, lA, hB, lB;
                split2pack(v0, v1, hA, lA);
                split2pack(v2, v3, hB, lB);
                *(uint32_t*)(Ch + offA) = hA;
                *(uint32_t*)(Cl + offA) = lA;
                *(uint32_t*)(Ch + offB) = hB;
                *(uint32_t*)(Cl + offB) = lB;
            } else {
                *(float2*)(C + offA) = make_float2(v0, v1);
                *(float2*)(C + offB) = make_float2(v2, v3);
            }
        }
    }
}

// ---------------------------------------------------------------------------
// Merged QKV GEMM (cp.async staging, 2 CTAs/SM). grid.x = 24, grid.y = 32.
// ---------------------------------------------------------------------------
__global__ __launch_bounds__(256, 2) void mm_qkv(
    const bf16* __restrict__ Ah, const bf16* __restrict__ Al,
    const bf16* __restrict__ B0h, const bf16* __restrict__ B0l,
    const bf16* __restrict__ B1h, const bf16* __restrict__ B1l,
    const bf16* __restrict__ B2h, const bf16* __restrict__ B2l,
    const float* __restrict__ bias0, const float* __restrict__ bias1,
    const float* __restrict__ bias2,
    bf16* __restrict__ C0h, bf16* __restrict__ C0l,
    bf16* __restrict__ C1h, bf16* __restrict__ C1l,
    bf16* __restrict__ C2h, bf16* __restrict__ C2l)
{
    extern __shared__ char smem[];
    const uint32_t sb = smem_u32(smem);
    const int tid = threadIdx.x, wid = tid >> 5, lid = tid & 31;
    const int wm = wid & 1, wn = wid >> 1;
    const int seg = blockIdx.x >> 3;
    const int m0 = blockIdx.y * 128, n0 = (blockIdx.x & 7) * 128;

    const bf16* Bh = (seg == 0) ? B0h : (seg == 1) ? B1h : B2h;
    const bf16* Bl = (seg == 0) ? B0l : (seg == 1) ? B1l : B2l;
    const float* bias = (seg == 0) ? bias0 : (seg == 1) ? bias1 : bias2;
    bf16* Ch = (seg == 0) ? C0h : (seg == 1) ? C1h : C2h;
    bf16* Cl = (seg == 0) ? C0l : (seg == 1) ? C1l : C2l;
    const float oscale = (seg == 0) ? 0.125f : 1.0f;

    const int r0_ = tid >> 2, c0_ = tid & 3;
    const int r1_ = r0_ + 64;

    const bf16* srcs[4] = { Ah, Al, Bh, Bl };
    const int   base4[4] = { m0, m0, n0, n0 };

    auto cpChunk = [&](int kt, int buf) {
        const uint32_t bb = sb + buf * BUFSZ;
        #pragma unroll
        for (int a = 0; a < 4; a++) {
            const bf16* s = srcs[a] + (size_t)base4[a] * DIM + kt * 32;
            cp16(bb + a * ARR_B + r0_ * 80 + c0_ * 16, s + (size_t)r0_ * DIM + c0_ * 8);
            cp16(bb + a * ARR_B + r1_ * 80 + c0_ * 16, s + (size_t)r1_ * DIM + c0_ * 8);
        }
        CP_COMMIT();
    };

    float acc[4][4][4] = {};

    const int arow = wm * 64 + (lid & 7) + ((lid >> 3) & 1) * 8;
    const uint32_t acolb = ((lid >> 4) & 1) * 16;
    const int brow = wn * 32 + (lid & 7) + ((lid >> 4) & 1) * 8;
    const uint32_t bcolb = ((lid >> 3) & 1) * 16;

    cpChunk(0, 0);
    CP_WAIT0();
    __syncthreads();

    const int nk = DIM >> 5;
    for (int kt = 0; kt < nk; kt++) {
        const int buf = kt & 1;
        if (kt + 1 < nk) cpChunk(kt + 1, buf ^ 1);

        const uint32_t bb = sb + buf * BUFSZ;
        #pragma unroll
        for (int kh = 0; kh < 2; kh++) {
            uint32_t ah[4][4], al[4][4], bh[4][2], bl[4][2];
            #pragma unroll
            for (int mf = 0; mf < 4; mf++) {
                const uint32_t ad = bb + (arow + mf * 16) * 80 + acolb + kh * 32;
                ldmx4(ah[mf], ad);
                ldmx4(al[mf], ad + ARR_B);
            }
            #pragma unroll
            for (int g2 = 0; g2 < 2; g2++) {
                const uint32_t bd = bb + 2 * ARR_B + (brow + g2 * 16) * 80 + bcolb + kh * 32;
                uint32_t t[4];
                ldmx4(t, bd);
                bh[g2*2][0] = t[0]; bh[g2*2][1] = t[1];
                bh[g2*2+1][0] = t[2]; bh[g2*2+1][1] = t[3];
                ldmx4(t, bd + ARR_B);
                bl[g2*2][0] = t[0]; bl[g2*2][1] = t[1];
                bl[g2*2+1][0] = t[2]; bl[g2*2+1][1] = t[3];
            }
            #pragma unroll
            for (int mf = 0; mf < 4; mf++)
                #pragma unroll
                for (int nf = 0; nf < 4; nf++) {
                    mma_bf16(acc[mf][nf], ah[mf], bh[nf]);
                    mma_bf16(acc[mf][nf], ah[mf], bl[nf]);
                    mma_bf16(acc[mf][nf], al[mf], bh[nf]);
                }
        }

        if (kt + 1 < nk) {
            CP_WAIT0();
            __syncthreads();
        }
    }

    #pragma unroll
    for (int mf = 0; mf < 4; mf++) {
        const int rowA = m0 + wm * 64 + mf * 16 + (lid >> 2);
        const int rowB = rowA + 8;
        #pragma unroll
        for (int nf = 0; nf < 4; nf++) {
            const int col = n0 + wn * 32 + nf * 8 + (lid & 3) * 2;
            const float2 b2 = *(const float2*)(bias + col);
            float v0 = (acc[mf][nf][0] + b2.x) * oscale;
            float v1 = (acc[mf][nf][1] + b2.y) * oscale;
            float v2 = (acc[mf][nf][2] + b2.x) * oscale;
            float v3 = (acc[mf][nf][3] + b2.y) * oscale;
            const size_t offA = (size_t)rowA * DIM + col;
            const size_t offB = (size_t)rowB * DIM + col;
            uint32_t hA, lA, hB, lB;
            split2pack(v0, v1, hA, lA);
            split2pack(v2, v3, hB, lB);
            *(uint32_t*)(Ch + offA) = hA;
            *(uint32_t*)(Cl + offA) = lA;
            *(uint32_t*)(Ch + offB) = hB;
            *(uint32_t*)(Cl + offB) = lB;
        }
    }
}

// ---------------------------------------------------------------------------
// Flash attention v4 (unchanged from R12 WIN).
// ---------------------------------------------------------------------------
#define AQ_B   18432u
#define AKV_B  9216u
#define KV0    (2u * AQ_B)
#define KVBUF  (4u * AKV_B)
#define ASMEM  (KV0 + 2u * KVBUF)

__global__ __launch_bounds__(128, 2) void attn_tc(
    const bf16* __restrict__ qh, const bf16* __restrict__ ql,
    const bf16* __restrict__ kh, const bf16* __restrict__ kl,
    const bf16* __restrict__ vh, const bf16* __restrict__ vl,
    bf16* __restrict__ oh, bf16* __restrict__ ol)
{
    extern __shared__ char smem[];
    const uint32_t sb = smem_u32(smem);
    const int tid = threadIdx.x, wid = tid >> 5, lid = tid & 31;
    const int bh_ = blockIdx.y;
    const int b = bh_ >> 4, h = bh_ & 15;
    const int q0 = blockIdx.x * 128;
    const size_t base = (size_t)(b * SEQ) * DIM + h * HD;

    auto cpKV = [&](int kt, int buf) {
        const size_t rowb = base + (size_t)(kt * 64) * DIM;
        const uint32_t bb = sb + KV0 + buf * KVBUF;
        #pragma unroll
        for (int u = 0; u < 4; u++) {
            const int idx = u * 128 + tid;
            const int r = idx >> 3, c8 = idx & 7;
            const size_t gp = rowb + (size_t)r * DIM + c8 * 8;
            const uint32_t so = r * 144 + c8 * 16;
            cp16(bb + 0*AKV_B + so, kh + gp);
            cp16(bb + 1*AKV_B + so, kl + gp);
            cp16(bb + 2*AKV_B + so, vh + gp);
            cp16(bb + 3*AKV_B + so, vl + gp);
        }
        CP_COMMIT();
    };

    cpKV(0, 0);
    #pragma unroll
    for (int it = 0; it < 8; it++) {
        const int idx = it * 128 + tid;
        const int r = idx >> 3, c8 = idx & 7;
        const size_t gp = base + (size_t)(q0 + r) * DIM + c8 * 8;
        *(uint4*)(smem + 0    + r * 144 + c8 * 16) = *(const uint4*)(qh + gp);
        *(uint4*)(smem + AQ_B + r * 144 + c8 * 16) = *(const uint4*)(ql + gp);
    }
    CP_WAIT0();
    __syncthreads();

    const int arowb = wid * 32 + (lid & 7) + ((lid >> 3) & 1) * 8;
    const uint32_t acol = ((lid >> 4) & 1) * 16;
    uint32_t Qh_[2][4][4];
    #pragma unroll
    for (int mt = 0; mt < 2; mt++)
        #pragma unroll
        for (int ks = 0; ks < 4; ks++)
            ldmx4(Qh_[mt][ks], sb + (arowb + mt * 16) * 144 + acol + ks * 32);

    float O[2][8][4] = {};
    float m_[2][2] = { {-1e30f, -1e30f}, {-1e30f, -1e30f} };
    float l_[2][2] = { {0.f, 0.f}, {0.f, 0.f} };

    const int brow = (lid & 7) + ((lid >> 4) & 1) * 8;
    const uint32_t bcol = ((lid >> 3) & 1) * 16;
    const int vrow = (lid & 7) + ((lid >> 3) & 1) * 8;
    const uint32_t vcole = ((lid >> 4) & 1) * 8;

    const int NT = SEQ / 64;
    for (int kt = 0; kt < NT; kt++) {
        const int buf = kt & 1;
        if (kt + 1 < NT) cpKV(kt + 1, buf ^ 1);

        const uint32_t kvb = sb + KV0 + buf * KVBUF;

        float S[2][8][4] = {};
        #pragma unroll
        for (int ks = 0; ks < 4; ks++) {
            uint32_t qlf[2][4];
            #pragma unroll
            for (int mt = 0; mt < 2; mt++)
                ldmx4(qlf[mt], sb + AQ_B + (arowb + mt * 16) * 144 + acol + ks * 32);
            #pragma unroll
            for (int g2 = 0; g2 < 4; g2++) {
                const uint32_t bd = kvb + (brow + g2 * 16) * 144 + bcol + ks * 32;
                uint32_t th[4], tl[4];
                ldmx4(th, bd);
                ldmx4(tl, bd + AKV_B);
                uint32_t bh0[2] = { th[0], th[1] }, bh1[2] = { th[2], th[3] };
                uint32_t bl0[2] = { tl[0], tl[1] }, bl1[2] = { tl[2], tl[3] };
                #pragma unroll
                for (int mt = 0; mt < 2; mt++) {
                    mma_bf16(S[mt][g2*2],   Qh_[mt][ks], bh0);
                    mma_bf16(S[mt][g2*2],   Qh_[mt][ks], bl0);
                    mma_bf16(S[mt][g2*2],   qlf[mt],     bh0);
                    mma_bf16(S[mt][g2*2+1], Qh_[mt][ks], bh1);
                    mma_bf16(S[mt][g2*2+1], Qh_[mt][ks], bl1);
                    mma_bf16(S[mt][g2*2+1], qlf[mt],     bh1);
                }
            }
        }

        #pragma unroll
        for (int mt = 0; mt < 2; mt++) {
            float rm0 = -1e30f, rm1 = -1e30f;
            #pragma unroll
            for (int nf = 0; nf < 8; nf++) {
                rm0 = fmaxf(rm0, fmaxf(S[mt][nf][0], S[mt][nf][1]));
                rm1 = fmaxf(rm1, fmaxf(S[mt][nf][2], S[mt][nf][3]));
            }
            rm0 = fmaxf(rm0, __shfl_xor_sync(0xffffffffu, rm0, 1));
            rm0 = fmaxf(rm0, __shfl_xor_sync(0xffffffffu, rm0, 2));
            rm1 = fmaxf(rm1, __shfl_xor_sync(0xffffffffu, rm1, 1));
            rm1 = fmaxf(rm1, __shfl_xor_sync(0xffffffffu, rm1, 2));
            const float mn0 = fmaxf(m_[mt][0], rm0), mn1 = fmaxf(m_[mt][1], rm1);
            const float c0 = __expf(m_[mt][0] - mn0), c1 = __expf(m_[mt][1] - mn1);
            m_[mt][0] = mn0; m_[mt][1] = mn1;

            float rs0 = 0.f, rs1 = 0.f;
            #pragma unroll
            for (int nf = 0; nf < 8; nf++) {
                S[mt][nf][0] = __expf(S[mt][nf][0] - mn0);
                S[mt][nf][1] = __expf(S[mt][nf][1] - mn0);
                S[mt][nf][2] = __expf(S[mt][nf][2] - mn1);
                S[mt][nf][3] = __expf(S[mt][nf][3] - mn1);
                rs0 += S[mt][nf][0] + S[mt][nf][1];
                rs1 += S[mt][nf][2] + S[mt][nf][3];
            }
            rs0 += __shfl_xor_sync(0xffffffffu, rs0, 1);
            rs0 += __shfl_xor_sync(0xffffffffu, rs0, 2);
            rs1 += __shfl_xor_sync(0xffffffffu, rs1, 1);
            rs1 += __shfl_xor_sync(0xffffffffu, rs1, 2);
            l_[mt][0] = l_[mt][0] * c0 + rs0;
            l_[mt][1] = l_[mt][1] * c1 + rs1;
            #pragma unroll
            for (int nf = 0; nf < 8; nf++) {
                O[mt][nf][0] *= c0; O[mt][nf][1] *= c0;
                O[mt][nf][2] *= c1; O[mt][nf][3] *= c1;
            }
        }

        uint32_t Ph[2][4][4], Pl[2][4][4];
        #pragma unroll
        for (int mt = 0; mt < 2; mt++)
            #pragma unroll
            for (int t = 0; t < 4; t++) {
                split2pack(S[mt][2*t][0],   S[mt][2*t][1],   Ph[mt][t][0], Pl[mt][t][0]);
                split2pack(S[mt][2*t][2],   S[mt][2*t][3],   Ph[mt][t][1], Pl[mt][t][1]);
                split2pack(S[mt][2*t+1][0], S[mt][2*t+1][1], Ph[mt][t][2], Pl[mt][t][2]);
                split2pack(S[mt][2*t+1][2], S[mt][2*t+1][3], Ph[mt][t][3], Pl[mt][t][3]);
            }

        #pragma unroll
        for (int t = 0; t < 4; t++) {
            #pragma unroll
            for (int g2 = 0; g2 < 4; g2++) {
                const uint32_t vd = kvb + 2*AKV_B +
                    (t * 16 + vrow) * 144 + (g2 * 16 + vcole) * 2;
                uint32_t th[4], tl[4];
                ldmx4t(th, vd);
                ldmx4t(tl, vd + AKV_B);
                uint32_t bh0[2] = { th[0], th[1] }, bh1[2] = { th[2], th[3] };
                uint32_t bl0[2] = { tl[0], tl[1] }, bl1[2] = { tl[2], tl[3] };
                #pragma unroll
                for (int mt = 0; mt < 2; mt++) {
                    mma_bf16(O[mt][g2*2],   Ph[mt][t], bh0);
                    mma_bf16(O[mt][g2*2],   Pl[mt][t], bh0);
                    mma_bf16(O[mt][g2*2],   Ph[mt][t], bl0);
                    mma_bf16(O[mt][g2*2+1], Ph[mt][t], bh1);
                    mma_bf16(O[mt][g2*2+1], Pl[mt][t], bh1);
                    mma_bf16(O[mt][g2*2+1], Ph[mt][t], bl1);
                }
            }
        }

        if (kt + 1 < NT) {
            CP_WAIT0();
            __syncthreads();
        }
    }

    #pragma unroll
    for (int mt = 0; mt < 2; mt++) {
        const float inv0 = 1.f / l_[mt][0], inv1 = 1.f / l_[mt][1];
        const int rowA = q0 + wid * 32 + mt * 16 + (lid >> 2);
        const int rowB = rowA + 8;
        #pragma unroll
        for (int nf = 0; nf < 8; nf++) {
            const int col = h * HD + nf * 8 + (lid & 3) * 2;
            const size_t offA = (size_t)(b * SEQ + rowA) * DIM + col;
            const size_t offB = (size_t)(b * SEQ + rowB) * DIM + col;
            uint32_t hA, lA, hB, lB;
            split2pack(O[mt][nf][0] * inv0, O[mt][nf][1] * inv0, hA, lA);
            split2pack(O[mt][nf][2] * inv1, O[mt][nf][3] * inv1, hB, lB);
            *(uint32_t*)(oh + offA) = hA;
            *(uint32_t*)(ol + offA) = lA;
            *(uint32_t*)(oh + offB) = hB;
            *(uint32_t*)(ol + offB) = lB;
        }
    }
}

// ---------------------------------------------------------------------------
extern "C" void kernel_launch(void* const* d_in, const int* in_sizes, int n_in,
                              void* d_out, int out_size)
{
    const float* x     = (const float*)d_in[0];
    const float* ln1_g = (const float*)d_in[1];
    const float* ln1_b = (const float*)d_in[2];
    const float* wq = (const float*)d_in[3];
    const float* bq = (const float*)d_in[4];
    const float* wk = (const float*)d_in[5];
    const float* bk = (const float*)d_in[6];
    const float* wv = (const float*)d_in[7];
    const float* bv = (const float*)d_in[8];
    const float* wo = (const float*)d_in[9];
    const float* bo = (const float*)d_in[10];
    const float* w1 = (const float*)d_in[11];
    const float* b1 = (const float*)d_in[12];
    const float* w2 = (const float*)d_in[13];
    const float* b2 = (const float*)d_in[14];
    const float* ln2_g = (const float*)d_in[15];
    const float* ln2_b = (const float*)d_in[16];
    float* out = (float*)d_out;

    bf16 *hh, *hl, *qh, *ql, *kh, *kl, *vh, *vl, *ath, *atl, *h2h, *h2l, *ffh, *ffl;
    bf16 *wqh, *wql, *wkh, *wkl, *wvh, *wvl, *woh, *wol, *w1h, *w1l, *w2h, *w2l;
    float *x1;
    cudaGetSymbolAddress((void**)&hh,  g_hh);  cudaGetSymbolAddress((void**)&hl,  g_hl);
    cudaGetSymbolAddress((void**)&qh,  g_qh);  cudaGetSymbolAddress((void**)&ql,  g_ql);
    cudaGetSymbolAddress((void**)&kh,  g_kh);  cudaGetSymbolAddress((void**)&kl,  g_kl);
    cudaGetSymbolAddress((void**)&vh,  g_vh);  cudaGetSymbolAddress((void**)&vl,  g_vl);
    cudaGetSymbolAddress((void**)&ath, g_ath); cudaGetSymbolAddress((void**)&atl, g_atl);
    cudaGetSymbolAddress((void**)&x1,  g_x1);
    cudaGetSymbolAddress((void**)&h2h, g_h2h); cudaGetSymbolAddress((void**)&h2l, g_h2l);
    cudaGetSymbolAddress((void**)&ffh, g_ffh); cudaGetSymbolAddress((void**)&ffl, g_ffl);
    cudaGetSymbolAddress((void**)&wqh, g_wqh); cudaGetSymbolAddress((void**)&wql, g_wql);
    cudaGetSymbolAddress((void**)&wkh, g_wkh); cudaGetSymbolAddress((void**)&wkl, g_wkl);
    cudaGetSymbolAddress((void**)&wvh, g_wvh); cudaGetSymbolAddress((void**)&wvl, g_wvl);
    cudaGetSymbolAddress((void**)&woh, g_woh); cudaGetSymbolAddress((void**)&wol, g_wol);
    cudaGetSymbolAddress((void**)&w1h, g_w1h); cudaGetSymbolAddress((void**)&w1l, g_w1l);
    cudaGetSymbolAddress((void**)&w2h, g_w2h); cudaGetSymbolAddress((void**)&w2l, g_w2l);

    cudaFuncSetAttribute(mm_tc<1>, cudaFuncAttributeMaxDynamicSharedMemorySize, MM_SMEM);
    cudaFuncSetAttribute(mm_tc<2>, cudaFuncAttributeMaxDynamicSharedMemorySize, MM_SMEM);
    cudaFuncSetAttribute(mm_qkv,   cudaFuncAttributeMaxDynamicSharedMemorySize, MM_SMEM);
    cudaFuncSetAttribute(attn_tc,  cudaFuncAttributeMaxDynamicSharedMemorySize, ASMEM);

    // weight transpose + split
    wsplit<<<dim3(DIM/32, DIM/32), 256>>>(wq, wqh, wql, DIM, DIM);
    wsplit<<<dim3(DIM/32, DIM/32), 256>>>(wk, wkh, wkl, DIM, DIM);
    wsplit<<<dim3(DIM/32, DIM/32), 256>>>(wv, wvh, wvl, DIM, DIM);
    wsplit<<<dim3(DIM/32, DIM/32), 256>>>(wo, woh, wol, DIM, DIM);
    wsplit<<<dim3(DFF/32, DIM/32), 256>>>(w1, w1h, w1l, DIM, DFF);
    wsplit<<<dim3(DIM/32, DFF/32), 256>>>(w2, w2h, w2l, DFF, DIM);

    const dim3 gD(DIM / 128, TOK / 128);
    const dim3 gF(DFF / 128, TOK / 128);

    ln_split<<<TOK, 256>>>(x, ln1_g, ln1_b, hh, hl);
    mm_qkv<<<dim3(24, TOK / 128), 256, MM_SMEM>>>(
        hh, hl, wqh, wql, wkh, wkl, wvh, wvl, bq, bk, bv,
        qh, ql, kh, kl, vh, vl);
    attn_tc<<<dim3(SEQ / 128, BATCH * NH), 128, ASMEM>>>(qh, ql, kh, kl, vh, vl, ath, atl);
    mm_tc<1><<<gD, 256, MM_SMEM>>>(ath, atl, woh, wol, bo, x, x1, nullptr, nullptr, TOK, DIM, DIM, 1.0f);
    ln_split<<<TOK, 256>>>(x1, ln2_g, ln2_b, h2h, h2l);
    mm_tc<2><<<gF, 256, MM_SMEM>>>(h2h, h2l, w1h, w1l, b1, nullptr, nullptr, ffh, ffl, TOK, DFF, DIM, 1.0f);
    mm_tc<1><<<gD, 256, MM_SMEM>>>(ffh, ffl, w2h, w2l, b2, x1, out, nullptr, nullptr, TOK, DIM, DFF, 1.0f);
}

// round 16
// speedup vs baseline: 1.2202x; 1.0543x over previous
#include <cuda_runtime.h>
#include <cuda_bf16.h>
#include <math.h>
#include <cstdint>

// ---------------------------------------------------------------------------
// Encoder_84413287236054 : fp32 transformer encoder layer on GB300
// Round 14: batch-split dual-stream graph (fork/join capture). Kernels
// unchanged from R13 WIN; launches operate on per-batch row ranges so the
// two chains overlap and fill each other's partial waves.
// ---------------------------------------------------------------------------

#define TOK  4096
#define DIM  1024
#define DFF  4096
#define NH   16
#define HD   64
#define SEQ  2048
#define BATCH 2

typedef unsigned long long u64;
typedef __nv_bfloat16 bf16;

// ---- tensor-core primitives (compute_103-legal) ----------------------------
__device__ __forceinline__ uint32_t smem_u32(const void* p) {
    uint32_t a;
    asm("{ .reg .u64 t; cvta.to.shared.u64 t, %1; cvt.u32.u64 %0, t; }" : "=r"(a) : "l"(p));
    return a;
}
__device__ __forceinline__ void ldmx4(uint32_t* r, uint32_t addr) {
    asm volatile("ldmatrix.sync.aligned.m8n8.x4.shared.b16 {%0,%1,%2,%3},[%4];"
        : "=r"(r[0]), "=r"(r[1]), "=r"(r[2]), "=r"(r[3]) : "r"(addr));
}
__device__ __forceinline__ void ldmx4t(uint32_t* r, uint32_t addr) {
    asm volatile("ldmatrix.sync.aligned.m8n8.x4.trans.shared.b16 {%0,%1,%2,%3},[%4];"
        : "=r"(r[0]), "=r"(r[1]), "=r"(r[2]), "=r"(r[3]) : "r"(addr));
}
__device__ __forceinline__ void mma_bf16(float* c, const uint32_t* a, const uint32_t* b) {
    asm volatile("mma.sync.aligned.m16n8k16.row.col.f32.bf16.bf16.f32 "
        "{%0,%1,%2,%3},{%4,%5,%6,%7},{%8,%9},{%0,%1,%2,%3};"
        : "+f"(c[0]), "+f"(c[1]), "+f"(c[2]), "+f"(c[3])
        : "r"(a[0]), "r"(a[1]), "r"(a[2]), "r"(a[3]), "r"(b[0]), "r"(b[1]));
}
__device__ __forceinline__ void cp16(uint32_t dst, const void* src) {
    asm volatile("cp.async.cg.shared.global [%0],[%1],16;" :: "r"(dst), "l"(src));
}
#define CP_COMMIT() asm volatile("cp.async.commit_group;" ::: "memory")
#define CP_WAIT0()  asm volatile("cp.async.wait_group 0;" ::: "memory")

__device__ __forceinline__ void split1(float x, bf16& h, bf16& l) {
    h = __float2bfloat16(x);
    l = __float2bfloat16(x - __bfloat162float(h));
}
__device__ __forceinline__ uint32_t packbf2(bf16 a, bf16 b) {
    __nv_bfloat162 t = __halves2bfloat162(a, b);
    return *(uint32_t*)&t;
}
__device__ __forceinline__ void split2pack(float a, float b, uint32_t& hp, uint32_t& lp) {
    bf16 ha, la, hb, lb;
    split1(a, ha, la); split1(b, hb, lb);
    hp = packbf2(ha, hb); lp = packbf2(la, lb);
}

// ---------------- scratch (allocation-free) ---------------------------------
__device__ bf16  g_hh [TOK * DIM], g_hl [TOK * DIM];
__device__ bf16  g_qh [TOK * DIM], g_ql [TOK * DIM];
__device__ bf16  g_kh [TOK * DIM], g_kl [TOK * DIM];
__device__ bf16  g_vh [TOK * DIM], g_vl [TOK * DIM];
__device__ bf16  g_ath[TOK * DIM], g_atl[TOK * DIM];
__device__ float g_x1 [TOK * DIM];
__device__ bf16  g_h2h[TOK * DIM], g_h2l[TOK * DIM];
__device__ bf16  g_ffh[TOK * DFF], g_ffl[TOK * DFF];
__device__ bf16 g_wqh[DIM * DIM], g_wql[DIM * DIM];
__device__ bf16 g_wkh[DIM * DIM], g_wkl[DIM * DIM];
__device__ bf16 g_wvh[DIM * DIM], g_wvl[DIM * DIM];
__device__ bf16 g_woh[DIM * DIM], g_wol[DIM * DIM];
__device__ bf16 g_w1h[DFF * DIM], g_w1l[DFF * DIM];
__device__ bf16 g_w2h[DIM * DFF], g_w2l[DIM * DFF];

// ---------------------------------------------------------------------------
// Weight transpose + hi/lo split: W[K,N] fp32 -> Th,Tl [N,K] bf16
// ---------------------------------------------------------------------------
__global__ __launch_bounds__(256) void wsplit(
    const float* __restrict__ W, bf16* __restrict__ Th, bf16* __restrict__ Tl,
    int K, int N)
{
    __shared__ float t[32][33];
    const int n0 = blockIdx.x * 32, k0 = blockIdx.y * 32;
    const int tx = threadIdx.x & 31, ty = threadIdx.x >> 5;
    #pragma unroll
    for (int i = ty; i < 32; i += 8)
        t[i][tx] = W[(size_t)(k0 + i) * N + n0 + tx];
    __syncthreads();
    #pragma unroll
    for (int i = ty; i < 32; i += 8) {
        const float x = t[tx][i];
        bf16 h, l; split1(x, h, l);
        Th[(size_t)(n0 + i) * K + k0 + tx] = h;
        Tl[(size_t)(n0 + i) * K + k0 + tx] = l;
    }
}

// ---------------------------------------------------------------------------
// LayerNorm -> bf16 hi/lo
// ---------------------------------------------------------------------------
__global__ __launch_bounds__(256) void ln_split(
    const float* __restrict__ x, const float* __restrict__ g,
    const float* __restrict__ b, bf16* __restrict__ oh, bf16* __restrict__ ol)
{
    const int row = blockIdx.x;
    const int t = threadIdx.x;
    const float4 v = ((const float4*)(x + (size_t)row * DIM))[t];

    float s  = v.x + v.y + v.z + v.w;
    float ss = v.x*v.x + v.y*v.y + v.z*v.z + v.w*v.w;
    #pragma unroll
    for (int o = 16; o; o >>= 1) {
        s  += __shfl_xor_sync(0xffffffffu, s,  o);
        ss += __shfl_xor_sync(0xffffffffu, ss, o);
    }
    __shared__ float sm[8], sm2[8];
    if ((t & 31) == 0) { sm[t >> 5] = s; sm2[t >> 5] = ss; }
    __syncthreads();
    float ts = 0.f, tss = 0.f;
    #pragma unroll
    for (int i = 0; i < 8; i++) { ts += sm[i]; tss += sm2[i]; }

    const float mu   = ts * (1.0f / DIM);
    const float rstd = rsqrtf(tss * (1.0f / DIM) - mu * mu + 1e-5f);
    const float4 gv = ((const float4*)g)[t];
    const float4 bv = ((const float4*)b)[t];
    float y[4];
    y[0] = (v.x - mu) * rstd * gv.x + bv.x;
    y[1] = (v.y - mu) * rstd * gv.y + bv.y;
    y[2] = (v.z - mu) * rstd * gv.z + bv.z;
    y[3] = (v.w - mu) * rstd * gv.w + bv.w;
    uint32_t hp0, lp0, hp1, lp1;
    split2pack(y[0], y[1], hp0, lp0);
    split2pack(y[2], y[3], hp1, lp1);
    *(uint2*)(oh + (size_t)row * DIM + t * 4) = make_uint2(hp0, hp1);
    *(uint2*)(ol + (size_t)row * DIM + t * 4) = make_uint2(lp0, lp1);
}

// ---------------------------------------------------------------------------
// Tensor-core GEMM: cp.async staging, 2 CTAs/SM. (unchanged from R13)
// ---------------------------------------------------------------------------
#define ARR_B  10240u
#define BUFSZ  40960u
#define MM_SMEM (2u * BUFSZ)

template<int EPI>
__global__ __launch_bounds__(256, 2) void mm_tc(
    const bf16* __restrict__ Ah, const bf16* __restrict__ Al,
    const bf16* __restrict__ Bh, const bf16* __restrict__ Bl,
    const float* __restrict__ bias, const float* __restrict__ res,
    float* __restrict__ C, bf16* __restrict__ Ch, bf16* __restrict__ Cl,
    int M, int N, int K, float oscale)
{
    extern __shared__ char smem[];
    const uint32_t sb = smem_u32(smem);
    const int tid = threadIdx.x, wid = tid >> 5, lid = tid & 31;
    const int wm = wid & 1, wn = wid >> 1;
    const int m0 = blockIdx.y * 128, n0 = blockIdx.x * 128;

    const int r0_ = tid >> 2, c0_ = tid & 3;
    const int r1_ = r0_ + 64;

    const bf16* srcs[4] = { Ah, Al, Bh, Bl };
    const int   base4[4] = { m0, m0, n0, n0 };

    auto cpChunk = [&](int kt, int buf) {
        const uint32_t bb = sb + buf * BUFSZ;
        #pragma unroll
        for (int a = 0; a < 4; a++) {
            const bf16* s = srcs[a] + (size_t)base4[a] * K + kt * 32;
            cp16(bb + a * ARR_B + r0_ * 80 + c0_ * 16, s + (size_t)r0_ * K + c0_ * 8);
            cp16(bb + a * ARR_B + r1_ * 80 + c0_ * 16, s + (size_t)r1_ * K + c0_ * 8);
        }
        CP_COMMIT();
    };

    float acc[4][4][4] = {};

    const int arow = wm * 64 + (lid & 7) + ((lid >> 3) & 1) * 8;
    const uint32_t acolb = ((lid >> 4) & 1) * 16;
    const int brow = wn * 32 + (lid & 7) + ((lid >> 4) & 1) * 8;
    const uint32_t bcolb = ((lid >> 3) & 1) * 16;

    cpChunk(0, 0);
    CP_WAIT0();
    __syncthreads();

    const int nk = K >> 5;
    for (int kt = 0; kt < nk; kt++) {
        const int buf = kt & 1;
        if (kt + 1 < nk) cpChunk(kt + 1, buf ^ 1);

        const uint32_t bb = sb + buf * BUFSZ;
        #pragma unroll
        for (int kh = 0; kh < 2; kh++) {
            uint32_t ah[4][4], al[4][4], bh[4][2], bl[4][2];
            #pragma unroll
            for (int mf = 0; mf < 4; mf++) {
                const uint32_t ad = bb + (arow + mf * 16) * 80 + acolb + kh * 32;
                ldmx4(ah[mf], ad);
                ldmx4(al[mf], ad + ARR_B);
            }
            #pragma unroll
            for (int g2 = 0; g2 < 2; g2++) {
                const uint32_t bd = bb + 2 * ARR_B + (brow + g2 * 16) * 80 + bcolb + kh * 32;
                uint32_t t[4];
                ldmx4(t, bd);
                bh[g2*2][0] = t[0]; bh[g2*2][1] = t[1];
                bh[g2*2+1][0] = t[2]; bh[g2*2+1][1] = t[3];
                ldmx4(t, bd + ARR_B);
                bl[g2*2][0] = t[0]; bl[g2*2][1] = t[1];
                bl[g2*2+1][0] = t[2]; bl[g2*2+1][1] = t[3];
            }
            #pragma unroll
            for (int mf = 0; mf < 4; mf++)
                #pragma unroll
                for (int nf = 0; nf < 4; nf++) {
                    mma_bf16(acc[mf][nf], ah[mf], bh[nf]);
                    mma_bf16(acc[mf][nf], ah[mf], bl[nf]);
                    mma_bf16(acc[mf][nf], al[mf], bh[nf]);
                }
        }

        if (kt + 1 < nk) {
            CP_WAIT0();
            __syncthreads();
        }
    }

    // ---------------- epilogue ----------------
    #pragma unroll
    for (int mf = 0; mf < 4; mf++) {
        const int rowA = m0 + wm * 64 + mf * 16 + (lid >> 2);
        const int rowB = rowA + 8;
        #pragma unroll
        for (int nf = 0; nf < 4; nf++) {
            const int col = n0 + wn * 32 + nf * 8 + (lid & 3) * 2;
            const float2 b2 = *(const float2*)(bias + col);
            float v0 = acc[mf][nf][0] + b2.x;
            float v1 = acc[mf][nf][1] + b2.y;
            float v2 = acc[mf][nf][2] + b2.x;
            float v3 = acc[mf][nf][3] + b2.y;
            const size_t offA = (size_t)rowA * N + col;
            const size_t offB = (size_t)rowB * N + col;
            if (EPI == 1) {
                const float2 rA = *(const float2*)(res + offA);
                const float2 rB = *(const float2*)(res + offB);
                v0 += rA.x; v1 += rA.y; v2 += rB.x; v3 += rB.y;
            }
            if (EPI == 2 || EPI == 3) {
                if (EPI == 2) {
                    v0 = v0 * normcdff(v0); v1 = v1 * normcdff(v1);
                    v2 = v2 * normcdff(v2); v3 = v3 * normcdff(v3);
                } else {
                    v0 *= oscale; v1 *= oscale; v2 *= oscale; v3 *= oscale;
                }
                uint32_t hA, lA, hB, lB;
                split2pack(v0, v1, hA, lA);
                split2pack(v2, v3, hB, lB);
                *(uint32_t*)(Ch + offA) = hA;
                *(uint32_t*)(Cl + offA) = lA;
                *(uint32_t*)(Ch + offB) = hB;
                *(uint32_t*)(Cl + offB) = lB;
            } else {
                *(float2*)(C + offA) = make_float2(v0, v1);
                *(float2*)(C + offB) = make_float2(v2, v3);
            }
        }
    }
}

// ---------------------------------------------------------------------------
// Merged QKV GEMM (cp.async staging, 2 CTAs/SM). (unchanged from R13)
// ---------------------------------------------------------------------------
__global__ __launch_bounds__(256, 2) void mm_qkv(
    const bf16* __restrict__ Ah, const bf16* __restrict__ Al,
    const bf16* __restrict__ B0h, const bf16* __restrict__ B0l,
    const bf16* __restrict__ B1h, const bf16* __restrict__ B1l,
    const bf16* __restrict__ B2h, const bf16* __restrict__ B2l,
    const float* __restrict__ bias0, const float* __restrict__ bias1,
    const float* __restrict__ bias2,
    bf16* __restrict__ C0h, bf16* __restrict__ C0l,
    bf16* __restrict__ C1h, bf16* __restrict__ C1l,
    bf16* __restrict__ C2h, bf16* __restrict__ C2l)
{
    extern __shared__ char smem[];
    const uint32_t sb = smem_u32(smem);
    const int tid = threadIdx.x, wid = tid >> 5, lid = tid & 31;
    const int wm = wid & 1, wn = wid >> 1;
    const int seg = blockIdx.x >> 3;
    const int m0 = blockIdx.y * 128, n0 = (blockIdx.x & 7) * 128;

    const bf16* Bh = (seg == 0) ? B0h : (seg == 1) ? B1h : B2h;
    const bf16* Bl = (seg == 0) ? B0l : (seg == 1) ? B1l : B2l;
    const float* bias = (seg == 0) ? bias0 : (seg == 1) ? bias1 : bias2;
    bf16* Ch = (seg == 0) ? C0h : (seg == 1) ? C1h : C2h;
    bf16* Cl = (seg == 0) ? C0l : (seg == 1) ? C1l : C2l;
    const float oscale = (seg == 0) ? 0.125f : 1.0f;

    const int r0_ = tid >> 2, c0_ = tid & 3;
    const int r1_ = r0_ + 64;

    const bf16* srcs[4] = { Ah, Al, Bh, Bl };
    const int   base4[4] = { m0, m0, n0, n0 };

    auto cpChunk = [&](int kt, int buf) {
        const uint32_t bb = sb + buf * BUFSZ;
        #pragma unroll
        for (int a = 0; a < 4; a++) {
            const bf16* s = srcs[a] + (size_t)base4[a] * DIM + kt * 32;
            cp16(bb + a * ARR_B + r0_ * 80 + c0_ * 16, s + (size_t)r0_ * DIM + c0_ * 8);
            cp16(bb + a * ARR_B + r1_ * 80 + c0_ * 16, s + (size_t)r1_ * DIM + c0_ * 8);
        }
        CP_COMMIT();
    };

    float acc[4][4][4] = {};

    const int arow = wm * 64 + (lid & 7) + ((lid >> 3) & 1) * 8;
    const uint32_t acolb = ((lid >> 4) & 1) * 16;
    const int brow = wn * 32 + (lid & 7) + ((lid >> 4) & 1) * 8;
    const uint32_t bcolb = ((lid >> 3) & 1) * 16;

    cpChunk(0, 0);
    CP_WAIT0();
    __syncthreads();

    const int nk = DIM >> 5;
    for (int kt = 0; kt < nk; kt++) {
        const int buf = kt & 1;
        if (kt + 1 < nk) cpChunk(kt + 1, buf ^ 1);

        const uint32_t bb = sb + buf * BUFSZ;
        #pragma unroll
        for (int kh = 0; kh < 2; kh++) {
            uint32_t ah[4][4], al[4][4], bh[4][2], bl[4][2];
            #pragma unroll
            for (int mf = 0; mf < 4; mf++) {
                const uint32_t ad = bb + (arow + mf * 16) * 80 + acolb + kh * 32;
                ldmx4(ah[mf], ad);
                ldmx4(al[mf], ad + ARR_B);
            }
            #pragma unroll
            for (int g2 = 0; g2 < 2; g2++) {
                const uint32_t bd = bb + 2 * ARR_B + (brow + g2 * 16) * 80 + bcolb + kh * 32;
                uint32_t t[4];
                ldmx4(t, bd);
                bh[g2*2][0] = t[0]; bh[g2*2][1] = t[1];
                bh[g2*2+1][0] = t[2]; bh[g2*2+1][1] = t[3];
                ldmx4(t, bd + ARR_B);
                bl[g2*2][0] = t[0]; bl[g2*2][1] = t[1];
                bl[g2*2+1][0] = t[2]; bl[g2*2+1][1] = t[3];
            }
            #pragma unroll
            for (int mf = 0; mf < 4; mf++)
                #pragma unroll
                for (int nf = 0; nf < 4; nf++) {
                    mma_bf16(acc[mf][nf], ah[mf], bh[nf]);
                    mma_bf16(acc[mf][nf], ah[mf], bl[nf]);
                    mma_bf16(acc[mf][nf], al[mf], bh[nf]);
                }
        }

        if (kt + 1 < nk) {
            CP_WAIT0();
            __syncthreads();
        }
    }

    #pragma unroll
    for (int mf = 0; mf < 4; mf++) {
        const int rowA = m0 + wm * 64 + mf * 16 + (lid >> 2);
        const int rowB = rowA + 8;
        #pragma unroll
        for (int nf = 0; nf < 4; nf++) {
            const int col = n0 + wn * 32 + nf * 8 + (lid & 3) * 2;
            const float2 b2 = *(const float2*)(bias + col);
            float v0 = (acc[mf][nf][0] + b2.x) * oscale;
            float v1 = (acc[mf][nf][1] + b2.y) * oscale;
            float v2 = (acc[mf][nf][2] + b2.x) * oscale;
            float v3 = (acc[mf][nf][3] + b2.y) * oscale;
            const size_t offA = (size_t)rowA * DIM + col;
            const size_t offB = (size_t)rowB * DIM + col;
            uint32_t hA, lA, hB, lB;
            split2pack(v0, v1, hA, lA);
            split2pack(v2, v3, hB, lB);
            *(uint32_t*)(Ch + offA) = hA;
            *(uint32_t*)(Cl + offA) = lA;
            *(uint32_t*)(Ch + offB) = hB;
            *(uint32_t*)(Cl + offB) = lB;
        }
    }
}

// ---------------------------------------------------------------------------
// Flash attention v4 (unchanged from R12/R13 WIN). Launch with grid.y = NH
// and batch-offset pointers (b resolves to 0 inside).
// ---------------------------------------------------------------------------
#define AQ_B   18432u
#define AKV_B  9216u
#define KV0    (2u * AQ_B)
#define KVBUF  (4u * AKV_B)
#define ASMEM  (KV0 + 2u * KVBUF)

__global__ __launch_bounds__(128, 2) void attn_tc(
    const bf16* __restrict__ qh, const bf16* __restrict__ ql,
    const bf16* __restrict__ kh, const bf16* __restrict__ kl,
    const bf16* __restrict__ vh, const bf16* __restrict__ vl,
    bf16* __restrict__ oh, bf16* __restrict__ ol)
{
    extern __shared__ char smem[];
    const uint32_t sb = smem_u32(smem);
    const int tid = threadIdx.x, wid = tid >> 5, lid = tid & 31;
    const int bh_ = blockIdx.y;
    const int b = bh_ >> 4, h = bh_ & 15;
    const int q0 = blockIdx.x * 128;
    const size_t base = (size_t)(b * SEQ) * DIM + h * HD;

    auto cpKV = [&](int kt, int buf) {
        const size_t rowb = base + (size_t)(kt * 64) * DIM;
        const uint32_t bb = sb + KV0 + buf * KVBUF;
        #pragma unroll
        for (int u = 0; u < 4; u++) {
            const int idx = u * 128 + tid;
            const int r = idx >> 3, c8 = idx & 7;
            const size_t gp = rowb + (size_t)r * DIM + c8 * 8;
            const uint32_t so = r * 144 + c8 * 16;
            cp16(bb + 0*AKV_B + so, kh + gp);
            cp16(bb + 1*AKV_B + so, kl + gp);
            cp16(bb + 2*AKV_B + so, vh + gp);
            cp16(bb + 3*AKV_B + so, vl + gp);
        }
        CP_COMMIT();
    };

    cpKV(0, 0);
    #pragma unroll
    for (int it = 0; it < 8; it++) {
        const int idx = it * 128 + tid;
        const int r = idx >> 3, c8 = idx & 7;
        const size_t gp = base + (size_t)(q0 + r) * DIM + c8 * 8;
        *(uint4*)(smem + 0    + r * 144 + c8 * 16) = *(const uint4*)(qh + gp);
        *(uint4*)(smem + AQ_B + r * 144 + c8 * 16) = *(const uint4*)(ql + gp);
    }
    CP_WAIT0();
    __syncthreads();

    const int arowb = wid * 32 + (lid & 7) + ((lid >> 3) & 1) * 8;
    const uint32_t acol = ((lid >> 4) & 1) * 16;
    uint32_t Qh_[2][4][4];
    #pragma unroll
    for (int mt = 0; mt < 2; mt++)
        #pragma unroll
        for (int ks = 0; ks < 4; ks++)
            ldmx4(Qh_[mt][ks], sb + (arowb + mt * 16) * 144 + acol + ks * 32);

    float O[2][8][4] = {};
    float m_[2][2] = { {-1e30f, -1e30f}, {-1e30f, -1e30f} };
    float l_[2][2] = { {0.f, 0.f}, {0.f, 0.f} };

    const int brow = (lid & 7) + ((lid >> 4) & 1) * 8;
    const uint32_t bcol = ((lid >> 3) & 1) * 16;
    const int vrow = (lid & 7) + ((lid >> 3) & 1) * 8;
    const uint32_t vcole = ((lid >> 4) & 1) * 8;

    const int NT = SEQ / 64;
    for (int kt = 0; kt < NT; kt++) {
        const int buf = kt & 1;
        if (kt + 1 < NT) cpKV(kt + 1, buf ^ 1);

        const uint32_t kvb = sb + KV0 + buf * KVBUF;

        float S[2][8][4] = {};
        #pragma unroll
        for (int ks = 0; ks < 4; ks++) {
            uint32_t qlf[2][4];
            #pragma unroll
            for (int mt = 0; mt < 2; mt++)
                ldmx4(qlf[mt], sb + AQ_B + (arowb + mt * 16) * 144 + acol + ks * 32);
            #pragma unroll
            for (int g2 = 0; g2 < 4; g2++) {
                const uint32_t bd = kvb + (brow + g2 * 16) * 144 + bcol + ks * 32;
                uint32_t th[4], tl[4];
                ldmx4(th, bd);
                ldmx4(tl, bd + AKV_B);
                uint32_t bh0[2] = { th[0], th[1] }, bh1[2] = { th[2], th[3] };
                uint32_t bl0[2] = { tl[0], tl[1] }, bl1[2] = { tl[2], tl[3] };
                #pragma unroll
                for (int mt = 0; mt < 2; mt++) {
                    mma_bf16(S[mt][g2*2],   Qh_[mt][ks], bh0);
                    mma_bf16(S[mt][g2*2],   Qh_[mt][ks], bl0);
                    mma_bf16(S[mt][g2*2],   qlf[mt],     bh0);
                    mma_bf16(S[mt][g2*2+1], Qh_[mt][ks], bh1);
                    mma_bf16(S[mt][g2*2+1], Qh_[mt][ks], bl1);
                    mma_bf16(S[mt][g2*2+1], qlf[mt],     bh1);
                }
            }
        }

        #pragma unroll
        for (int mt = 0; mt < 2; mt++) {
            float rm0 = -1e30f, rm1 = -1e30f;
            #pragma unroll
            for (int nf = 0; nf < 8; nf++) {
                rm0 = fmaxf(rm0, fmaxf(S[mt][nf][0], S[mt][nf][1]));
                rm1 = fmaxf(rm1, fmaxf(S[mt][nf][2], S[mt][nf][3]));
            }
            rm0 = fmaxf(rm0, __shfl_xor_sync(0xffffffffu, rm0, 1));
            rm0 = fmaxf(rm0, __shfl_xor_sync(0xffffffffu, rm0, 2));
            rm1 = fmaxf(rm1, __shfl_xor_sync(0xffffffffu, rm1, 1));
            rm1 = fmaxf(rm1, __shfl_xor_sync(0xffffffffu, rm1, 2));
            const float mn0 = fmaxf(m_[mt][0], rm0), mn1 = fmaxf(m_[mt][1], rm1);
            const float c0 = __expf(m_[mt][0] - mn0), c1 = __expf(m_[mt][1] - mn1);
            m_[mt][0] = mn0; m_[mt][1] = mn1;

            float rs0 = 0.f, rs1 = 0.f;
            #pragma unroll
            for (int nf = 0; nf < 8; nf++) {
                S[mt][nf][0] = __expf(S[mt][nf][0] - mn0);
                S[mt][nf][1] = __expf(S[mt][nf][1] - mn0);
                S[mt][nf][2] = __expf(S[mt][nf][2] - mn1);
                S[mt][nf][3] = __expf(S[mt][nf][3] - mn1);
                rs0 += S[mt][nf][0] + S[mt][nf][1];
                rs1 += S[mt][nf][2] + S[mt][nf][3];
            }
            rs0 += __shfl_xor_sync(0xffffffffu, rs0, 1);
            rs0 += __shfl_xor_sync(0xffffffffu, rs0, 2);
            rs1 += __shfl_xor_sync(0xffffffffu, rs1, 1);
            rs1 += __shfl_xor_sync(0xffffffffu, rs1, 2);
            l_[mt][0] = l_[mt][0] * c0 + rs0;
            l_[mt][1] = l_[mt][1] * c1 + rs1;
            #pragma unroll
            for (int nf = 0; nf < 8; nf++) {
                O[mt][nf][0] *= c0; O[mt][nf][1] *= c0;
                O[mt][nf][2] *= c1; O[mt][nf][3] *= c1;
            }
        }

        uint32_t Ph[2][4][4], Pl[2][4][4];
        #pragma unroll
        for (int mt = 0; mt < 2; mt++)
            #pragma unroll
            for (int t = 0; t < 4; t++) {
                split2pack(S[mt][2*t][0],   S[mt][2*t][1],   Ph[mt][t][0], Pl[mt][t][0]);
                split2pack(S[mt][2*t][2],   S[mt][2*t][3],   Ph[mt][t][1], Pl[mt][t][1]);
                split2pack(S[mt][2*t+1][0], S[mt][2*t+1][1], Ph[mt][t][2], Pl[mt][t][2]);
                split2pack(S[mt][2*t+1][2], S[mt][2*t+1][3], Ph[mt][t][3], Pl[mt][t][3]);
            }

        #pragma unroll
        for (int t = 0; t < 4; t++) {
            #pragma unroll
            for (int g2 = 0; g2 < 4; g2++) {
                const uint32_t vd = kvb + 2*AKV_B +
                    (t * 16 + vrow) * 144 + (g2 * 16 + vcole) * 2;
                uint32_t th[4], tl[4];
                ldmx4t(th, vd);
                ldmx4t(tl, vd + AKV_B);
                uint32_t bh0[2] = { th[0], th[1] }, bh1[2] = { th[2], th[3] };
                uint32_t bl0[2] = { tl[0], tl[1] }, bl1[2] = { tl[2], tl[3] };
                #pragma unroll
                for (int mt = 0; mt < 2; mt++) {
                    mma_bf16(O[mt][g2*2],   Ph[mt][t], bh0);
                    mma_bf16(O[mt][g2*2],   Pl[mt][t], bh0);
                    mma_bf16(O[mt][g2*2],   Ph[mt][t], bl0);
                    mma_bf16(O[mt][g2*2+1], Ph[mt][t], bh1);
                    mma_bf16(O[mt][g2*2+1], Pl[mt][t], bh1);
                    mma_bf16(O[mt][g2*2+1], Ph[mt][t], bl1);
                }
            }
        }

        if (kt + 1 < NT) {
            CP_WAIT0();
            __syncthreads();
        }
    }

    #pragma unroll
    for (int mt = 0; mt < 2; mt++) {
        const float inv0 = 1.f / l_[mt][0], inv1 = 1.f / l_[mt][1];
        const int rowA = q0 + wid * 32 + mt * 16 + (lid >> 2);
        const int rowB = rowA + 8;
        #pragma unroll
        for (int nf = 0; nf < 8; nf++) {
            const int col = h * HD + nf * 8 + (lid & 3) * 2;
            const size_t offA = (size_t)(b * SEQ + rowA) * DIM + col;
            const size_t offB = (size_t)(b * SEQ + rowB) * DIM + col;
            uint32_t hA, lA, hB, lB;
            split2pack(O[mt][nf][0] * inv0, O[mt][nf][1] * inv0, hA, lA);
            split2pack(O[mt][nf][2] * inv1, O[mt][nf][3] * inv1, hB, lB);
            *(uint32_t*)(oh + offA) = hA;
            *(uint32_t*)(ol + offA) = lA;
            *(uint32_t*)(oh + offB) = hB;
            *(uint32_t*)(ol + offB) = lB;
        }
    }
}

// ---------------------------------------------------------------------------
// Launch: dual-stream batch-split graph (fork/join via events).
// ---------------------------------------------------------------------------
static cudaStream_t g_s1 = nullptr, g_s2 = nullptr;
static cudaEvent_t  g_e0, g_e1, g_e2, g_e3;

extern "C" void kernel_launch(void* const* d_in, const int* in_sizes, int n_in,
                              void* d_out, int out_size)
{
    const float* x     = (const float*)d_in[0];
    const float* ln1_g = (const float*)d_in[1];
    const float* ln1_b = (const float*)d_in[2];
    const float* wq = (const float*)d_in[3];
    const float* bq = (const float*)d_in[4];
    const float* wk = (const float*)d_in[5];
    const float* bk = (const float*)d_in[6];
    const float* wv = (const float*)d_in[7];
    const float* bv = (const float*)d_in[8];
    const float* wo = (const float*)d_in[9];
    const float* bo = (const float*)d_in[10];
    const float* w1 = (const float*)d_in[11];
    const float* b1 = (const float*)d_in[12];
    const float* w2 = (const float*)d_in[13];
    const float* b2 = (const float*)d_in[14];
    const float* ln2_g = (const float*)d_in[15];
    const float* ln2_b = (const float*)d_in[16];
    float* out = (float*)d_out;

    bf16 *hh, *hl, *qh, *ql, *kh, *kl, *vh, *vl, *ath, *atl, *h2h, *h2l, *ffh, *ffl;
    bf16 *wqh, *wql, *wkh, *wkl, *wvh, *wvl, *woh, *wol, *w1h, *w1l, *w2h, *w2l;
    float *x1;
    cudaGetSymbolAddress((void**)&hh,  g_hh);  cudaGetSymbolAddress((void**)&hl,  g_hl);
    cudaGetSymbolAddress((void**)&qh,  g_qh);  cudaGetSymbolAddress((void**)&ql,  g_ql);
    cudaGetSymbolAddress((void**)&kh,  g_kh);  cudaGetSymbolAddress((void**)&kl,  g_kl);
    cudaGetSymbolAddress((void**)&vh,  g_vh);  cudaGetSymbolAddress((void**)&vl,  g_vl);
    cudaGetSymbolAddress((void**)&ath, g_ath); cudaGetSymbolAddress((void**)&atl, g_atl);
    cudaGetSymbolAddress((void**)&x1,  g_x1);
    cudaGetSymbolAddress((void**)&h2h, g_h2h); cudaGetSymbolAddress((void**)&h2l, g_h2l);
    cudaGetSymbolAddress((void**)&ffh, g_ffh); cudaGetSymbolAddress((void**)&ffl, g_ffl);
    cudaGetSymbolAddress((void**)&wqh, g_wqh); cudaGetSymbolAddress((void**)&wql, g_wql);
    cudaGetSymbolAddress((void**)&wkh, g_wkh); cudaGetSymbolAddress((void**)&wkl, g_wkl);
    cudaGetSymbolAddress((void**)&wvh, g_wvh); cudaGetSymbolAddress((void**)&wvl, g_wvl);
    cudaGetSymbolAddress((void**)&woh, g_woh); cudaGetSymbolAddress((void**)&wol, g_wol);
    cudaGetSymbolAddress((void**)&w1h, g_w1h); cudaGetSymbolAddress((void**)&w1l, g_w1l);
    cudaGetSymbolAddress((void**)&w2h, g_w2h); cudaGetSymbolAddress((void**)&w2l, g_w2l);

    cudaFuncSetAttribute(mm_tc<1>, cudaFuncAttributeMaxDynamicSharedMemorySize, MM_SMEM);
    cudaFuncSetAttribute(mm_tc<2>, cudaFuncAttributeMaxDynamicSharedMemorySize, MM_SMEM);
    cudaFuncSetAttribute(mm_qkv,   cudaFuncAttributeMaxDynamicSharedMemorySize, MM_SMEM);
    cudaFuncSetAttribute(attn_tc,  cudaFuncAttributeMaxDynamicSharedMemorySize, ASMEM);

    if (g_s1 == nullptr) {
        cudaStreamCreateWithFlags(&g_s1, cudaStreamNonBlocking);
        cudaStreamCreateWithFlags(&g_s2, cudaStreamNonBlocking);
        cudaEventCreateWithFlags(&g_e0, cudaEventDisableTiming);
        cudaEventCreateWithFlags(&g_e1, cudaEventDisableTiming);
        cudaEventCreateWithFlags(&g_e2, cudaEventDisableTiming);
        cudaEventCreateWithFlags(&g_e3, cudaEventDisableTiming);
    }

    // --- side stream s1: weight transpose+split, concurrent with LN1 ------
    cudaEventRecord(g_e0, 0);
    cudaStreamWaitEvent(g_s1, g_e0, 0);
    wsplit<<<dim3(DIM/32, DIM/32), 256, 0, g_s1>>>(wq, wqh, wql, DIM, DIM);
    wsplit<<<dim3(DIM/32, DIM/32), 256, 0, g_s1>>>(wk, wkh, wkl, DIM, DIM);
    wsplit<<<dim3(DIM/32, DIM/32), 256, 0, g_s1>>>(wv, wvh, wvl, DIM, DIM);
    wsplit<<<dim3(DIM/32, DIM/32), 256, 0, g_s1>>>(wo, woh, wol, DIM, DIM);
    wsplit<<<dim3(DFF/32, DIM/32), 256, 0, g_s1>>>(w1, w1h, w1l, DIM, DFF);
    wsplit<<<dim3(DIM/32, DFF/32), 256, 0, g_s1>>>(w2, w2h, w2l, DFF, DIM);

    ln_split<<<TOK, 256>>>(x, ln1_g, ln1_b, hh, hl);      // main stream

    cudaEventRecord(g_e1, g_s1);
    cudaStreamWaitEvent(0, g_e1, 0);                      // join: weights+LN1

    // --- fork per-batch chains: batch 0 on main stream, batch 1 on s2 ------
    cudaEventRecord(g_e2, 0);
    cudaStreamWaitEvent(g_s2, g_e2, 0);

    auto chain = [&](cudaStream_t st, int batch) {
        const size_t ro = (size_t)batch * SEQ * DIM;      // row offset (elems)
        const size_t rf = (size_t)batch * SEQ * DFF;
        mm_qkv<<<dim3(24, SEQ/128), 256, MM_SMEM, st>>>(
            hh + ro, hl + ro, wqh, wql, wkh, wkl, wvh, wvl, bq, bk, bv,
            qh + ro, ql + ro, kh + ro, kl + ro, vh + ro, vl + ro);
        attn_tc<<<dim3(SEQ/128, NH), 128, ASMEM, st>>>(
            qh + ro, ql + ro, kh + ro, kl + ro, vh + ro, vl + ro,
            ath + ro, atl + ro);
        mm_tc<1><<<dim3(DIM/128, SEQ/128), 256, MM_SMEM, st>>>(
            ath + ro, atl + ro, woh, wol, bo, x + ro, x1 + ro,
            nullptr, nullptr, SEQ, DIM, DIM, 1.0f);
        ln_split<<<SEQ, 256, 0, st>>>(x1 + ro, ln2_g, ln2_b, h2h + ro, h2l + ro);
        mm_tc<2><<<dim3(DFF/128, SEQ/128), 256, MM_SMEM, st>>>(
            h2h + ro, h2l + ro, w1h, w1l, b1, nullptr, nullptr,
            ffh + rf, ffl + rf, SEQ, DFF, DIM, 1.0f);
        mm_tc<1><<<dim3(DIM/128, SEQ/128), 256, MM_SMEM, st>>>(
            ffh + rf, ffl + rf, w2h, w2l, b2, x1 + ro, out + ro,
            nullptr, nullptr, SEQ, DIM, DFF, 1.0f);
    };
    chain((cudaStream_t)0, 0);    // batch 0, main stream
    chain(g_s2, 1);               // batch 1, side stream

    cudaEventRecord(g_e3, g_s2);
    cudaStreamWaitEvent(0, g_e3, 0);                      // join
}

// round 17
// speedup vs baseline: 1.2415x; 1.0174x over previous
#include <cuda_runtime.h>
#include <cuda_bf16.h>
#include <math.h>
#include <cstdint>

// ---------------------------------------------------------------------------
// Encoder_84413287236054 : fp32 transformer encoder layer on GB300
// Round 17: per-batch LN1 inside chains; wsplit gated in two groups (QKV
// weights gate mm_qkv; Wo/W1/W2 gate the Wo GEMM ~400us later); softmax in
// exp2 domain (log2e folded into Q scale). Kernels otherwise R13/R16.
// ---------------------------------------------------------------------------

#define TOK  4096
#define DIM  1024
#define DFF  4096
#define NH   16
#define HD   64
#define SEQ  2048
#define BATCH 2

typedef unsigned long long u64;
typedef __nv_bfloat16 bf16;

// 0.125 * log2(e): QK scores land pre-scaled for exp2-domain softmax
#define QSCALE 0.18033688011112042f

// ---- tensor-core primitives (compute_103-legal) ----------------------------
__device__ __forceinline__ uint32_t smem_u32(const void* p) {
    uint32_t a;
    asm("{ .reg .u64 t; cvta.to.shared.u64 t, %1; cvt.u32.u64 %0, t; }" : "=r"(a) : "l"(p));
    return a;
}
__device__ __forceinline__ void ldmx4(uint32_t* r, uint32_t addr) {
    asm volatile("ldmatrix.sync.aligned.m8n8.x4.shared.b16 {%0,%1,%2,%3},[%4];"
        : "=r"(r[0]), "=r"(r[1]), "=r"(r[2]), "=r"(r[3]) : "r"(addr));
}
__device__ __forceinline__ void ldmx4t(uint32_t* r, uint32_t addr) {
    asm volatile("ldmatrix.sync.aligned.m8n8.x4.trans.shared.b16 {%0,%1,%2,%3},[%4];"
        : "=r"(r[0]), "=r"(r[1]), "=r"(r[2]), "=r"(r[3]) : "r"(addr));
}
__device__ __forceinline__ void mma_bf16(float* c, const uint32_t* a, const uint32_t* b) {
    asm volatile("mma.sync.aligned.m16n8k16.row.col.f32.bf16.bf16.f32 "
        "{%0,%1,%2,%3},{%4,%5,%6,%7},{%8,%9},{%0,%1,%2,%3};"
        : "+f"(c[0]), "+f"(c[1]), "+f"(c[2]), "+f"(c[3])
        : "r"(a[0]), "r"(a[1]), "r"(a[2]), "r"(a[3]), "r"(b[0]), "r"(b[1]));
}
__device__ __forceinline__ void cp16(uint32_t dst, const void* src) {
    asm volatile("cp.async.cg.shared.global [%0],[%1],16;" :: "r"(dst), "l"(src));
}
#define CP_COMMIT() asm volatile("cp.async.commit_group;" ::: "memory")
#define CP_WAIT0()  asm volatile("cp.async.wait_group 0;" ::: "memory")

__device__ __forceinline__ void split1(float x, bf16& h, bf16& l) {
    h = __float2bfloat16(x);
    l = __float2bfloat16(x - __bfloat162float(h));
}
__device__ __forceinline__ uint32_t packbf2(bf16 a, bf16 b) {
    __nv_bfloat162 t = __halves2bfloat162(a, b);
    return *(uint32_t*)&t;
}
__device__ __forceinline__ void split2pack(float a, float b, uint32_t& hp, uint32_t& lp) {
    bf16 ha, la, hb, lb;
    split1(a, ha, la); split1(b, hb, lb);
    hp = packbf2(ha, hb); lp = packbf2(la, lb);
}

// ---------------- scratch (allocation-free) ---------------------------------
__device__ bf16  g_hh [TOK * DIM], g_hl [TOK * DIM];
__device__ bf16  g_qh [TOK * DIM], g_ql [TOK * DIM];
__device__ bf16  g_kh [TOK * DIM], g_kl [TOK * DIM];
__device__ bf16  g_vh [TOK * DIM], g_vl [TOK * DIM];
__device__ bf16  g_ath[TOK * DIM], g_atl[TOK * DIM];
__device__ float g_x1 [TOK * DIM];
__device__ bf16  g_h2h[TOK * DIM], g_h2l[TOK * DIM];
__device__ bf16  g_ffh[TOK * DFF], g_ffl[TOK * DFF];
__device__ bf16 g_wqh[DIM * DIM], g_wql[DIM * DIM];
__device__ bf16 g_wkh[DIM * DIM], g_wkl[DIM * DIM];
__device__ bf16 g_wvh[DIM * DIM], g_wvl[DIM * DIM];
__device__ bf16 g_woh[DIM * DIM], g_wol[DIM * DIM];
__device__ bf16 g_w1h[DFF * DIM], g_w1l[DFF * DIM];
__device__ bf16 g_w2h[DIM * DFF], g_w2l[DIM * DFF];

// ---------------------------------------------------------------------------
// Weight transpose + hi/lo split: W[K,N] fp32 -> Th,Tl [N,K] bf16
// ---------------------------------------------------------------------------
__global__ __launch_bounds__(256) void wsplit(
    const float* __restrict__ W, bf16* __restrict__ Th, bf16* __restrict__ Tl,
    int K, int N)
{
    __shared__ float t[32][33];
    const int n0 = blockIdx.x * 32, k0 = blockIdx.y * 32;
    const int tx = threadIdx.x & 31, ty = threadIdx.x >> 5;
    #pragma unroll
    for (int i = ty; i < 32; i += 8)
        t[i][tx] = W[(size_t)(k0 + i) * N + n0 + tx];
    __syncthreads();
    #pragma unroll
    for (int i = ty; i < 32; i += 8) {
        const float x = t[tx][i];
        bf16 h, l; split1(x, h, l);
        Th[(size_t)(n0 + i) * K + k0 + tx] = h;
        Tl[(size_t)(n0 + i) * K + k0 + tx] = l;
    }
}

// ---------------------------------------------------------------------------
// LayerNorm -> bf16 hi/lo
// ---------------------------------------------------------------------------
__global__ __launch_bounds__(256) void ln_split(
    const float* __restrict__ x, const float* __restrict__ g,
    const float* __restrict__ b, bf16* __restrict__ oh, bf16* __restrict__ ol)
{
    const int row = blockIdx.x;
    const int t = threadIdx.x;
    const float4 v = ((const float4*)(x + (size_t)row * DIM))[t];

    float s  = v.x + v.y + v.z + v.w;
    float ss = v.x*v.x + v.y*v.y + v.z*v.z + v.w*v.w;
    #pragma unroll
    for (int o = 16; o; o >>= 1) {
        s  += __shfl_xor_sync(0xffffffffu, s,  o);
        ss += __shfl_xor_sync(0xffffffffu, ss, o);
    }
    __shared__ float sm[8], sm2[8];
    if ((t & 31) == 0) { sm[t >> 5] = s; sm2[t >> 5] = ss; }
    __syncthreads();
    float ts = 0.f, tss = 0.f;
    #pragma unroll
    for (int i = 0; i < 8; i++) { ts += sm[i]; tss += sm2[i]; }

    const float mu   = ts * (1.0f / DIM);
    const float rstd = rsqrtf(tss * (1.0f / DIM) - mu * mu + 1e-5f);
    const float4 gv = ((const float4*)g)[t];
    const float4 bv = ((const float4*)b)[t];
    float y[4];
    y[0] = (v.x - mu) * rstd * gv.x + bv.x;
    y[1] = (v.y - mu) * rstd * gv.y + bv.y;
    y[2] = (v.z - mu) * rstd * gv.z + bv.z;
    y[3] = (v.w - mu) * rstd * gv.w + bv.w;
    uint32_t hp0, lp0, hp1, lp1;
    split2pack(y[0], y[1], hp0, lp0);
    split2pack(y[2], y[3], hp1, lp1);
    *(uint2*)(oh + (size_t)row * DIM + t * 4) = make_uint2(hp0, hp1);
    *(uint2*)(ol + (size_t)row * DIM + t * 4) = make_uint2(lp0, lp1);
}

// ---------------------------------------------------------------------------
// Tensor-core GEMM: cp.async staging, 2 CTAs/SM. (unchanged from R13)
// ---------------------------------------------------------------------------
#define ARR_B  10240u
#define BUFSZ  40960u
#define MM_SMEM (2u * BUFSZ)

template<int EPI>
__global__ __launch_bounds__(256, 2) void mm_tc(
    const bf16* __restrict__ Ah, const bf16* __restrict__ Al,
    const bf16* __restrict__ Bh, const bf16* __restrict__ Bl,
    const float* __restrict__ bias, const float* __restrict__ res,
    float* __restrict__ C, bf16* __restrict__ Ch, bf16* __restrict__ Cl,
    int M, int N, int K, float oscale)
{
    extern __shared__ char smem[];
    const uint32_t sb = smem_u32(smem);
    const int tid = threadIdx.x, wid = tid >> 5, lid = tid & 31;
    const int wm = wid & 1, wn = wid >> 1;
    const int m0 = blockIdx.y * 128, n0 = blockIdx.x * 128;

    const int r0_ = tid >> 2, c0_ = tid & 3;
    const int r1_ = r0_ + 64;

    const bf16* srcs[4] = { Ah, Al, Bh, Bl };
    const int   base4[4] = { m0, m0, n0, n0 };

    auto cpChunk = [&](int kt, int buf) {
        const uint32_t bb = sb + buf * BUFSZ;
        #pragma unroll
        for (int a = 0; a < 4; a++) {
            const bf16* s = srcs[a] + (size_t)base4[a] * K + kt * 32;
            cp16(bb + a * ARR_B + r0_ * 80 + c0_ * 16, s + (size_t)r0_ * K + c0_ * 8);
            cp16(bb + a * ARR_B + r1_ * 80 + c0_ * 16, s + (size_t)r1_ * K + c0_ * 8);
        }
        CP_COMMIT();
    };

    float acc[4][4][4] = {};

    const int arow = wm * 64 + (lid & 7) + ((lid >> 3) & 1) * 8;
    const uint32_t acolb = ((lid >> 4) & 1) * 16;
    const int brow = wn * 32 + (lid & 7) + ((lid >> 4) & 1) * 8;
    const uint32_t bcolb = ((lid >> 3) & 1) * 16;

    cpChunk(0, 0);
    CP_WAIT0();
    __syncthreads();

    const int nk = K >> 5;
    for (int kt = 0; kt < nk; kt++) {
        const int buf = kt & 1;
        if (kt + 1 < nk) cpChunk(kt + 1, buf ^ 1);

        const uint32_t bb = sb + buf * BUFSZ;
        #pragma unroll
        for (int kh = 0; kh < 2; kh++) {
            uint32_t ah[4][4], al[4][4], bh[4][2], bl[4][2];
            #pragma unroll
            for (int mf = 0; mf < 4; mf++) {
                const uint32_t ad = bb + (arow + mf * 16) * 80 + acolb + kh * 32;
                ldmx4(ah[mf], ad);
                ldmx4(al[mf], ad + ARR_B);
            }
            #pragma unroll
            for (int g2 = 0; g2 < 2; g2++) {
                const uint32_t bd = bb + 2 * ARR_B + (brow + g2 * 16) * 80 + bcolb + kh * 32;
                uint32_t t[4];
                ldmx4(t, bd);
                bh[g2*2][0] = t[0]; bh[g2*2][1] = t[1];
                bh[g2*2+1][0] = t[2]; bh[g2*2+1][1] = t[3];
                ldmx4(t, bd + ARR_B);
                bl[g2*2][0] = t[0]; bl[g2*2][1] = t[1];
                bl[g2*2+1][0] = t[2]; bl[g2*2+1][1] = t[3];
            }
            #pragma unroll
            for (int mf = 0; mf < 4; mf++)
                #pragma unroll
                for (int nf = 0; nf < 4; nf++) {
                    mma_bf16(acc[mf][nf], ah[mf], bh[nf]);
                    mma_bf16(acc[mf][nf], ah[mf], bl[nf]);
                    mma_bf16(acc[mf][nf], al[mf], bh[nf]);
                }
        }

        if (kt + 1 < nk) {
            CP_WAIT0();
            __syncthreads();
        }
    }

    // ---------------- epilogue ----------------
    #pragma unroll
    for (int mf = 0; mf < 4; mf++) {
        const int rowA = m0 + wm * 64 + mf * 16 + (lid >> 2);
        const int rowB = rowA + 8;
        #pragma unroll
        for (int nf = 0; nf < 4; nf++) {
            const int col = n0 + wn * 32 + nf * 8 + (lid & 3) * 2;
            const float2 b2 = *(const float2*)(bias + col);
            float v0 = acc[mf][nf][0] + b2.x;
            float v1 = acc[mf][nf][1] + b2.y;
            float v2 = acc[mf][nf][2] + b2.x;
            float v3 = acc[mf][nf][3] + b2.y;
            const size_t offA = (size_t)rowA * N + col;
            const size_t offB = (size_t)rowB * N + col;
            if (EPI == 1) {
                const float2 rA = *(const float2*)(res + offA);
                const float2 rB = *(const float2*)(res + offB);
                v0 += rA.x; v1 += rA.y; v2 += rB.x; v3 += rB.y;
            }
            if (EPI == 2 || EPI == 3) {
                if (EPI == 2) {
                    v0 = v0 * normcdff(v0); v1 = v1 * normcdff(v1);
                    v2 = v2 * normcdff(v2); v3 = v3 * normcdff(v3);
                } else {
                    v0 *= oscale; v1 *= oscale; v2 *= oscale; v3 *= oscale;
                }
                uint32_t hA, lA, hB, lB;
                split2pack(v0, v1, hA, lA);
                split2pack(v2, v3, hB, lB);
                *(uint32_t*)(Ch + offA) = hA;
                *(uint32_t*)(Cl + offA) = lA;
                *(uint32_t*)(Ch + offB) = hB;
                *(uint32_t*)(Cl + offB) = lB;
            } else {
                *(float2*)(C + offA) = make_float2(v0, v1);
                *(float2*)(C + offB) = make_float2(v2, v3);
            }
        }
    }
}

// ---------------------------------------------------------------------------
// Merged QKV GEMM (cp.async staging, 2 CTAs/SM). Q scaled by QSCALE
// (1/sqrt(hd) * log2(e)) for exp2-domain softmax.
// ---------------------------------------------------------------------------
__global__ __launch_bounds__(256, 2) void mm_qkv(
    const bf16* __restrict__ Ah, const bf16* __restrict__ Al,
    const bf16* __restrict__ B0h, const bf16* __restrict__ B0l,
    const bf16* __restrict__ B1h, const bf16* __restrict__ B1l,
    const bf16* __restrict__ B2h, const bf16* __restrict__ B2l,
    const float* __restrict__ bias0, const float* __restrict__ bias1,
    const float* __restrict__ bias2,
    bf16* __restrict__ C0h, bf16* __restrict__ C0l,
    bf16* __restrict__ C1h, bf16* __restrict__ C1l,
    bf16* __restrict__ C2h, bf16* __restrict__ C2l)
{
    extern __shared__ char smem[];
    const uint32_t sb = smem_u32(smem);
    const int tid = threadIdx.x, wid = tid >> 5, lid = tid & 31;
    const int wm = wid & 1, wn = wid >> 1;
    const int seg = blockIdx.x >> 3;
    const int m0 = blockIdx.y * 128, n0 = (blockIdx.x & 7) * 128;

    const bf16* Bh = (seg == 0) ? B0h : (seg == 1) ? B1h : B2h;
    const bf16* Bl = (seg == 0) ? B0l : (seg == 1) ? B1l : B2l;
    const float* bias = (seg == 0) ? bias0 : (seg == 1) ? bias1 : bias2;
    bf16* Ch = (seg == 0) ? C0h : (seg == 1) ? C1h : C2h;
    bf16* Cl = (seg == 0) ? C0l : (seg == 1) ? C1l : C2l;
    const float oscale = (seg == 0) ? QSCALE : 1.0f;

    const int r0_ = tid >> 2, c0_ = tid & 3;
    const int r1_ = r0_ + 64;

    const bf16* srcs[4] = { Ah, Al, Bh, Bl };
    const int   base4[4] = { m0, m0, n0, n0 };

    auto cpChunk = [&](int kt, int buf) {
        const uint32_t bb = sb + buf * BUFSZ;
        #pragma unroll
        for (int a = 0; a < 4; a++) {
            const bf16* s = srcs[a] + (size_t)base4[a] * DIM + kt * 32;
            cp16(bb + a * ARR_B + r0_ * 80 + c0_ * 16, s + (size_t)r0_ * DIM + c0_ * 8);
            cp16(bb + a * ARR_B + r1_ * 80 + c0_ * 16, s + (size_t)r1_ * DIM + c0_ * 8);
        }
        CP_COMMIT();
    };

    float acc[4][4][4] = {};

    const int arow = wm * 64 + (lid & 7) + ((lid >> 3) & 1) * 8;
    const uint32_t acolb = ((lid >> 4) & 1) * 16;
    const int brow = wn * 32 + (lid & 7) + ((lid >> 4) & 1) * 8;
    const uint32_t bcolb = ((lid >> 3) & 1) * 16;

    cpChunk(0, 0);
    CP_WAIT0();
    __syncthreads();

    const int nk = DIM >> 5;
    for (int kt = 0; kt < nk; kt++) {
        const int buf = kt & 1;
        if (kt + 1 < nk) cpChunk(kt + 1, buf ^ 1);

        const uint32_t bb = sb + buf * BUFSZ;
        #pragma unroll
        for (int kh = 0; kh < 2; kh++) {
            uint32_t ah[4][4], al[4][4], bh[4][2], bl[4][2];
            #pragma unroll
            for (int mf = 0; mf < 4; mf++) {
                const uint32_t ad = bb + (arow + mf * 16) * 80 + acolb + kh * 32;
                ldmx4(ah[mf], ad);
                ldmx4(al[mf], ad + ARR_B);
            }
            #pragma unroll
            for (int g2 = 0; g2 < 2; g2++) {
                const uint32_t bd = bb + 2 * ARR_B + (brow + g2 * 16) * 80 + bcolb + kh * 32;
                uint32_t t[4];
                ldmx4(t, bd);
                bh[g2*2][0] = t[0]; bh[g2*2][1] = t[1];
                bh[g2*2+1][0] = t[2]; bh[g2*2+1][1] = t[3];
                ldmx4(t, bd + ARR_B);
                bl[g2*2][0] = t[0]; bl[g2*2][1] = t[1];
                bl[g2*2+1][0] = t[2]; bl[g2*2+1][1] = t[3];
            }
            #pragma unroll
            for (int mf = 0; mf < 4; mf++)
                #pragma unroll
                for (int nf = 0; nf < 4; nf++) {
                    mma_bf16(acc[mf][nf], ah[mf], bh[nf]);
                    mma_bf16(acc[mf][nf], ah[mf], bl[nf]);
                    mma_bf16(acc[mf][nf], al[mf], bh[nf]);
                }
        }

        if (kt + 1 < nk) {
            CP_WAIT0();
            __syncthreads();
        }
    }

    #pragma unroll
    for (int mf = 0; mf < 4; mf++) {
        const int rowA = m0 + wm * 64 + mf * 16 + (lid >> 2);
        const int rowB = rowA + 8;
        #pragma unroll
        for (int nf = 0; nf < 4; nf++) {
            const int col = n0 + wn * 32 + nf * 8 + (lid & 3) * 2;
            const float2 b2 = *(const float2*)(bias + col);
            float v0 = (acc[mf][nf][0] + b2.x) * oscale;
            float v1 = (acc[mf][nf][1] + b2.y) * oscale;
            float v2 = (acc[mf][nf][2] + b2.x) * oscale;
            float v3 = (acc[mf][nf][3] + b2.y) * oscale;
            const size_t offA = (size_t)rowA * DIM + col;
            const size_t offB = (size_t)rowB * DIM + col;
            uint32_t hA, lA, hB, lB;
            split2pack(v0, v1, hA, lA);
            split2pack(v2, v3, hB, lB);
            *(uint32_t*)(Ch + offA) = hA;
            *(uint32_t*)(Cl + offA) = lA;
            *(uint32_t*)(Ch + offB) = hB;
            *(uint32_t*)(Cl + offB) = lB;
        }
    }
}

// ---------------------------------------------------------------------------
// Flash attention v4 (exp2-domain softmax; scores arrive pre-scaled by
// log2e/sqrt(hd)). Launch grid.y = NH with batch-offset pointers.
// ---------------------------------------------------------------------------
#define AQ_B   18432u
#define AKV_B  9216u
#define KV0    (2u * AQ_B)
#define KVBUF  (4u * AKV_B)
#define ASMEM  (KV0 + 2u * KVBUF)

__global__ __launch_bounds__(128, 2) void attn_tc(
    const bf16* __restrict__ qh, const bf16* __restrict__ ql,
    const bf16* __restrict__ kh, const bf16* __restrict__ kl,
    const bf16* __restrict__ vh, const bf16* __restrict__ vl,
    bf16* __restrict__ oh, bf16* __restrict__ ol)
{
    extern __shared__ char smem[];
    const uint32_t sb = smem_u32(smem);
    const int tid = threadIdx.x, wid = tid >> 5, lid = tid & 31;
    const int bh_ = blockIdx.y;
    const int b = bh_ >> 4, h = bh_ & 15;
    const int q0 = blockIdx.x * 128;
    const size_t base = (size_t)(b * SEQ) * DIM + h * HD;

    auto cpKV = [&](int kt, int buf) {
        const size_t rowb = base + (size_t)(kt * 64) * DIM;
        const uint32_t bb = sb + KV0 + buf * KVBUF;
        #pragma unroll
        for (int u = 0; u < 4; u++) {
            const int idx = u * 128 + tid;
            const int r = idx >> 3, c8 = idx & 7;
            const size_t gp = rowb + (size_t)r * DIM + c8 * 8;
            const uint32_t so = r * 144 + c8 * 16;
            cp16(bb + 0*AKV_B + so, kh + gp);
            cp16(bb + 1*AKV_B + so, kl + gp);
            cp16(bb + 2*AKV_B + so, vh + gp);
            cp16(bb + 3*AKV_B + so, vl + gp);
        }
        CP_COMMIT();
    };

    cpKV(0, 0);
    #pragma unroll
    for (int it = 0; it < 8; it++) {
        const int idx = it * 128 + tid;
        const int r = idx >> 3, c8 = idx & 7;
        const size_t gp = base + (size_t)(q0 + r) * DIM + c8 * 8;
        *(uint4*)(smem + 0    + r * 144 + c8 * 16) = *(const uint4*)(qh + gp);
        *(uint4*)(smem + AQ_B + r * 144 + c8 * 16) = *(const uint4*)(ql + gp);
    }
    CP_WAIT0();
    __syncthreads();

    const int arowb = wid * 32 + (lid & 7) + ((lid >> 3) & 1) * 8;
    const uint32_t acol = ((lid >> 4) & 1) * 16;
    uint32_t Qh_[2][4][4];
    #pragma unroll
    for (int mt = 0; mt < 2; mt++)
        #pragma unroll
        for (int ks = 0; ks < 4; ks++)
            ldmx4(Qh_[mt][ks], sb + (arowb + mt * 16) * 144 + acol + ks * 32);

    float O[2][8][4] = {};
    float m_[2][2] = { {-1e30f, -1e30f}, {-1e30f, -1e30f} };
    float l_[2][2] = { {0.f, 0.f}, {0.f, 0.f} };

    const int brow = (lid & 7) + ((lid >> 4) & 1) * 8;
    const uint32_t bcol = ((lid >> 3) & 1) * 16;
    const int vrow = (lid & 7) + ((lid >> 3) & 1) * 8;
    const uint32_t vcole = ((lid >> 4) & 1) * 8;

    const int NT = SEQ / 64;
    for (int kt = 0; kt < NT; kt++) {
        const int buf = kt & 1;
        if (kt + 1 < NT) cpKV(kt + 1, buf ^ 1);

        const uint32_t kvb = sb + KV0 + buf * KVBUF;

        float S[2][8][4] = {};
        #pragma unroll
        for (int ks = 0; ks < 4; ks++) {
            uint32_t qlf[2][4];
            #pragma unroll
            for (int mt = 0; mt < 2; mt++)
                ldmx4(qlf[mt], sb + AQ_B + (arowb + mt * 16) * 144 + acol + ks * 32);
            #pragma unroll
            for (int g2 = 0; g2 < 4; g2++) {
                const uint32_t bd = kvb + (brow + g2 * 16) * 144 + bcol + ks * 32;
                uint32_t th[4], tl[4];
                ldmx4(th, bd);
                ldmx4(tl, bd + AKV_B);
                uint32_t bh0[2] = { th[0], th[1] }, bh1[2] = { th[2], th[3] };
                uint32_t bl0[2] = { tl[0], tl[1] }, bl1[2] = { tl[2], tl[3] };
                #pragma unroll
                for (int mt = 0; mt < 2; mt++) {
                    mma_bf16(S[mt][g2*2],   Qh_[mt][ks], bh0);
                    mma_bf16(S[mt][g2*2],   Qh_[mt][ks], bl0);
                    mma_bf16(S[mt][g2*2],   qlf[mt],     bh0);
                    mma_bf16(S[mt][g2*2+1], Qh_[mt][ks], bh1);
                    mma_bf16(S[mt][g2*2+1], Qh_[mt][ks], bl1);
                    mma_bf16(S[mt][g2*2+1], qlf[mt],     bh1);
                }
            }
        }

        #pragma unroll
        for (int mt = 0; mt < 2; mt++) {
            float rm0 = -1e30f, rm1 = -1e30f;
            #pragma unroll
            for (int nf = 0; nf < 8; nf++) {
                rm0 = fmaxf(rm0, fmaxf(S[mt][nf][0], S[mt][nf][1]));
                rm1 = fmaxf(rm1, fmaxf(S[mt][nf][2], S[mt][nf][3]));
            }
            rm0 = fmaxf(rm0, __shfl_xor_sync(0xffffffffu, rm0, 1));
            rm0 = fmaxf(rm0, __shfl_xor_sync(0xffffffffu, rm0, 2));
            rm1 = fmaxf(rm1, __shfl_xor_sync(0xffffffffu, rm1, 1));
            rm1 = fmaxf(rm1, __shfl_xor_sync(0xffffffffu, rm1, 2));
            const float mn0 = fmaxf(m_[mt][0], rm0), mn1 = fmaxf(m_[mt][1], rm1);
            const float c0 = exp2f(m_[mt][0] - mn0), c1 = exp2f(m_[mt][1] - mn1);
            m_[mt][0] = mn0; m_[mt][1] = mn1;

            float rs0 = 0.f, rs1 = 0.f;
            #pragma unroll
            for (int nf = 0; nf < 8; nf++) {
                S[mt][nf][0] = exp2f(S[mt][nf][0] - mn0);
                S[mt][nf][1] = exp2f(S[mt][nf][1] - mn0);
                S[mt][nf][2] = exp2f(S[mt][nf][2] - mn1);
                S[mt][nf][3] = exp2f(S[mt][nf][3] - mn1);
                rs0 += S[mt][nf][0] + S[mt][nf][1];
                rs1 += S[mt][nf][2] + S[mt][nf][3];
            }
            rs0 += __shfl_xor_sync(0xffffffffu, rs0, 1);
            rs0 += __shfl_xor_sync(0xffffffffu, rs0, 2);
            rs1 += __shfl_xor_sync(0xffffffffu, rs1, 1);
            rs1 += __shfl_xor_sync(0xffffffffu, rs1, 2);
            l_[mt][0] = l_[mt][0] * c0 + rs0;
            l_[mt][1] = l_[mt][1] * c1 + rs1;
            #pragma unroll
            for (int nf = 0; nf < 8; nf++) {
                O[mt][nf][0] *= c0; O[mt][nf][1] *= c0;
                O[mt][nf][2] *= c1; O[mt][nf][3] *= c1;
            }
        }

        uint32_t Ph[2][4][4], Pl[2][4][4];
        #pragma unroll
        for (int mt = 0; mt < 2; mt++)
            #pragma unroll
            for (int t = 0; t < 4; t++) {
                split2pack(S[mt][2*t][0],   S[mt][2*t][1],   Ph[mt][t][0], Pl[mt][t][0]);
                split2pack(S[mt][2*t][2],   S[mt][2*t][3],   Ph[mt][t][1], Pl[mt][t][1]);
                split2pack(S[mt][2*t+1][0], S[mt][2*t+1][1], Ph[mt][t][2], Pl[mt][t][2]);
                split2pack(S[mt][2*t+1][2], S[mt][2*t+1][3], Ph[mt][t][3], Pl[mt][t][3]);
            }

        #pragma unroll
        for (int t = 0; t < 4; t++) {
            #pragma unroll
            for (int g2 = 0; g2 < 4; g2++) {
                const uint32_t vd = kvb + 2*AKV_B +
                    (t * 16 + vrow) * 144 + (g2 * 16 + vcole) * 2;
                uint32_t th[4], tl[4];
                ldmx4t(th, vd);
                ldmx4t(tl, vd + AKV_B);
                uint32_t bh0[2] = { th[0], th[1] }, bh1[2] = { th[2], th[3] };
                uint32_t bl0[2] = { tl[0], tl[1] }, bl1[2] = { tl[2], tl[3] };
                #pragma unroll
                for (int mt = 0; mt < 2; mt++) {
                    mma_bf16(O[mt][g2*2],   Ph[mt][t], bh0);
                    mma_bf16(O[mt][g2*2],   Pl[mt][t], bh0);
                    mma_bf16(O[mt][g2*2],   Ph[mt][t], bl0);
                    mma_bf16(O[mt][g2*2+1], Ph[mt][t], bh1);
                    mma_bf16(O[mt][g2*2+1], Pl[mt][t], bh1);
                    mma_bf16(O[mt][g2*2+1], Ph[mt][t], bl1);
                }
            }
        }

        if (kt + 1 < NT) {
            CP_WAIT0();
            __syncthreads();
        }
    }

    #pragma unroll
    for (int mt = 0; mt < 2; mt++) {
        const float inv0 = 1.f / l_[mt][0], inv1 = 1.f / l_[mt][1];
        const int rowA = q0 + wid * 32 + mt * 16 + (lid >> 2);
        const int rowB = rowA + 8;
        #pragma unroll
        for (int nf = 0; nf < 8; nf++) {
            const int col = h * HD + nf * 8 + (lid & 3) * 2;
            const size_t offA = (size_t)(b * SEQ + rowA) * DIM + col;
            const size_t offB = (size_t)(b * SEQ + rowB) * DIM + col;
            uint32_t hA, lA, hB, lB;
            split2pack(O[mt][nf][0] * inv0, O[mt][nf][1] * inv0, hA, lA);
            split2pack(O[mt][nf][2] * inv1, O[mt][nf][3] * inv1, hB, lB);
            *(uint32_t*)(oh + offA) = hA;
            *(uint32_t*)(ol + offA) = lA;
            *(uint32_t*)(oh + offB) = hB;
            *(uint32_t*)(ol + offB) = lB;
        }
    }
}

// ---------------------------------------------------------------------------
// Launch: dual-stream batch-split graph; wsplit gated in two groups;
// per-batch LN1 inside each chain.
// ---------------------------------------------------------------------------
static cudaStream_t g_s1 = nullptr, g_s2 = nullptr;
static cudaEvent_t  g_e0, g_eA, g_eB, g_e3;

extern "C" void kernel_launch(void* const* d_in, const int* in_sizes, int n_in,
                              void* d_out, int out_size)
{
    const float* x     = (const float*)d_in[0];
    const float* ln1_g = (const float*)d_in[1];
    const float* ln1_b = (const float*)d_in[2];
    const float* wq = (const float*)d_in[3];
    const float* bq = (const float*)d_in[4];
    const float* wk = (const float*)d_in[5];
    const float* bk = (const float*)d_in[6];
    const float* wv = (const float*)d_in[7];
    const float* bv = (const float*)d_in[8];
    const float* wo = (const float*)d_in[9];
    const float* bo = (const float*)d_in[10];
    const float* w1 = (const float*)d_in[11];
    const float* b1 = (const float*)d_in[12];
    const float* w2 = (const float*)d_in[13];
    const float* b2 = (const float*)d_in[14];
    const float* ln2_g = (const float*)d_in[15];
    const float* ln2_b = (const float*)d_in[16];
    float* out = (float*)d_out;

    bf16 *hh, *hl, *qh, *ql, *kh, *kl, *vh, *vl, *ath, *atl, *h2h, *h2l, *ffh, *ffl;
    bf16 *wqh, *wql, *wkh, *wkl, *wvh, *wvl, *woh, *wol, *w1h, *w1l, *w2h, *w2l;
    float *x1;
    cudaGetSymbolAddress((void**)&hh,  g_hh);  cudaGetSymbolAddress((void**)&hl,  g_hl);
    cudaGetSymbolAddress((void**)&qh,  g_qh);  cudaGetSymbolAddress((void**)&ql,  g_ql);
    cudaGetSymbolAddress((void**)&kh,  g_kh);  cudaGetSymbolAddress((void**)&kl,  g_kl);
    cudaGetSymbolAddress((void**)&vh,  g_vh);  cudaGetSymbolAddress((void**)&vl,  g_vl);
    cudaGetSymbolAddress((void**)&ath, g_ath); cudaGetSymbolAddress((void**)&atl, g_atl);
    cudaGetSymbolAddress((void**)&x1,  g_x1);
    cudaGetSymbolAddress((void**)&h2h, g_h2h); cudaGetSymbolAddress((void**)&h2l, g_h2l);
    cudaGetSymbolAddress((void**)&ffh, g_ffh); cudaGetSymbolAddress((void**)&ffl, g_ffl);
    cudaGetSymbolAddress((void**)&wqh, g_wqh); cudaGetSymbolAddress((void**)&wql, g_wql);
    cudaGetSymbolAddress((void**)&wkh, g_wkh); cudaGetSymbolAddress((void**)&wkl, g_wkl);
    cudaGetSymbolAddress((void**)&wvh, g_wvh); cudaGetSymbolAddress((void**)&wvl, g_wvl);
    cudaGetSymbolAddress((void**)&woh, g_woh); cudaGetSymbolAddress((void**)&wol, g_wol);
    cudaGetSymbolAddress((void**)&w1h, g_w1h); cudaGetSymbolAddress((void**)&w1l, g_w1l);
    cudaGetSymbolAddress((void**)&w2h, g_w2h); cudaGetSymbolAddress((void**)&w2l, g_w2l);

    cudaFuncSetAttribute(mm_tc<1>, cudaFuncAttributeMaxDynamicSharedMemorySize, MM_SMEM);
    cudaFuncSetAttribute(mm_tc<2>, cudaFuncAttributeMaxDynamicSharedMemorySize, MM_SMEM);
    cudaFuncSetAttribute(mm_qkv,   cudaFuncAttributeMaxDynamicSharedMemorySize, MM_SMEM);
    cudaFuncSetAttribute(attn_tc,  cudaFuncAttributeMaxDynamicSharedMemorySize, ASMEM);

    if (g_s1 == nullptr) {
        cudaStreamCreateWithFlags(&g_s1, cudaStreamNonBlocking);
        cudaStreamCreateWithFlags(&g_s2, cudaStreamNonBlocking);
        cudaEventCreateWithFlags(&g_e0, cudaEventDisableTiming);
        cudaEventCreateWithFlags(&g_eA, cudaEventDisableTiming);
        cudaEventCreateWithFlags(&g_eB, cudaEventDisableTiming);
        cudaEventCreateWithFlags(&g_e3, cudaEventDisableTiming);
    }

    // fork: s1 (weights) and s2 (batch-1 chain) branch off the main stream
    cudaEventRecord(g_e0, 0);
    cudaStreamWaitEvent(g_s1, g_e0, 0);
    cudaStreamWaitEvent(g_s2, g_e0, 0);

    // s1 group A: QKV weights (gates mm_qkv in both chains)
    wsplit<<<dim3(DIM/32, DIM/32), 256, 0, g_s1>>>(wq, wqh, wql, DIM, DIM);
    wsplit<<<dim3(DIM/32, DIM/32), 256, 0, g_s1>>>(wk, wkh, wkl, DIM, DIM);
    wsplit<<<dim3(DIM/32, DIM/32), 256, 0, g_s1>>>(wv, wvh, wvl, DIM, DIM);
    cudaEventRecord(g_eA, g_s1);
    // s1 group B: Wo/W1/W2 weights (gates the Wo GEMM, ~400us of slack)
    wsplit<<<dim3(DIM/32, DIM/32), 256, 0, g_s1>>>(wo, woh, wol, DIM, DIM);
    wsplit<<<dim3(DFF/32, DIM/32), 256, 0, g_s1>>>(w1, w1h, w1l, DIM, DFF);
    wsplit<<<dim3(DIM/32, DFF/32), 256, 0, g_s1>>>(w2, w2h, w2l, DFF, DIM);
    cudaEventRecord(g_eB, g_s1);

    auto chain = [&](cudaStream_t st, int batch) {
        const size_t ro = (size_t)batch * SEQ * DIM;
        const size_t rf = (size_t)batch * SEQ * DFF;
        ln_split<<<SEQ, 256, 0, st>>>(x + ro, ln1_g, ln1_b, hh + ro, hl + ro);
        cudaStreamWaitEvent(st, g_eA, 0);
        mm_qkv<<<dim3(24, SEQ/128), 256, MM_SMEM, st>>>(
            hh + ro, hl + ro, wqh, wql, wkh, wkl, wvh, wvl, bq, bk, bv,
            qh + ro, ql + ro, kh + ro, kl + ro, vh + ro, vl + ro);
        attn_tc<<<dim3(SEQ/128, NH), 128, ASMEM, st>>>(
            qh + ro, ql + ro, kh + ro, kl + ro, vh + ro, vl + ro,
            ath + ro, atl + ro);
        cudaStreamWaitEvent(st, g_eB, 0);
        mm_tc<1><<<dim3(DIM/128, SEQ/128), 256, MM_SMEM, st>>>(
            ath + ro, atl + ro, woh, wol, bo, x + ro, x1 + ro,
            nullptr, nullptr, SEQ, DIM, DIM, 1.0f);
        ln_split<<<SEQ, 256, 0, st>>>(x1 + ro, ln2_g, ln2_b, h2h + ro, h2l + ro);
        mm_tc<2><<<dim3(DFF/128, SEQ/128), 256, MM_SMEM, st>>>(
            h2h + ro, h2l + ro, w1h, w1l, b1, nullptr, nullptr,
            ffh + rf, ffl + rf, SEQ, DFF, DIM, 1.0f);
        mm_tc<1><<<dim3(DIM/128, SEQ/128), 256, MM_SMEM, st>>>(
            ffh + rf, ffl + rf, w2h, w2l, b2, x1 + ro, out + ro,
            nullptr, nullptr, SEQ, DIM, DFF, 1.0f);
    };
    chain((cudaStream_t)0, 0);    // batch 0, main stream
    chain(g_s2, 1);               // batch 1, side stream

    cudaEventRecord(g_e3, g_s2);
    cudaStreamWaitEvent(0, g_e3, 0);                      // join
}